// round 1
// baseline (speedup 1.0000x reference)
#include <cuda_runtime.h>

#define BM 128
#define BN 128
#define BK 16
#define TM 8
#define TN 8
#define NT 256

#define B_ 4
#define S_ 2048
#define D_ 1024
#define P_ 1024

// Scratch (static device allocations — allowed; no dynamic allocs anywhere).
__device__ float g_Q[(long long)B_ * S_ * P_];
__device__ float g_K[(long long)B_ * S_ * P_];
__device__ float g_V[(long long)B_ * S_ * P_];
__device__ float g_S[(long long)B_ * S_ * S_];

// C[m,n] = sum_k A[m,k] * B[n,k]   (A:[M,K] row-major, B:[N,K] row-major)
// Used for QKV projections (x @ W^T) and scores (Q @ K^T, causal tile-skip).
__global__ __launch_bounds__(NT) void gemm_nt(
    const float* __restrict__ A, const float* __restrict__ B, float* __restrict__ C,
    int M, int N, int K,
    long long sA, long long sB, long long sC, int causal)
{
    const int m0 = blockIdx.y * BM;
    const int n0 = blockIdx.x * BN;
    if (causal && n0 > m0) return;  // tile fully above diagonal: never read downstream

    A += (long long)blockIdx.z * sA;
    B += (long long)blockIdx.z * sB;
    C += (long long)blockIdx.z * sC;

    __shared__ float As[BK][BM + 4];
    __shared__ float Bs[BK][BN + 4];

    const int tid = threadIdx.x;
    const int ty = tid >> 4;      // 0..15
    const int tx = tid & 15;      // 0..15

    float acc[TM][TN];
    #pragma unroll
    for (int i = 0; i < TM; i++)
        #pragma unroll
        for (int j = 0; j < TN; j++) acc[i][j] = 0.f;

    for (int k0 = 0; k0 < K; k0 += BK) {
        // Load A tile (BM x BK) and B tile (BN x BK), transposed into smem.
        #pragma unroll
        for (int l = 0; l < 2; ++l) {
            int v = tid + l * NT;           // 0..511
            int r = v >> 2;                 // row within tile (0..127)
            int c = (v & 3) << 2;           // k-offset (0,4,8,12)
            float4 a = *(const float4*)(A + (long long)(m0 + r) * K + k0 + c);
            As[c + 0][r] = a.x; As[c + 1][r] = a.y;
            As[c + 2][r] = a.z; As[c + 3][r] = a.w;
            float4 b = *(const float4*)(B + (long long)(n0 + r) * K + k0 + c);
            Bs[c + 0][r] = b.x; Bs[c + 1][r] = b.y;
            Bs[c + 2][r] = b.z; Bs[c + 3][r] = b.w;
        }
        __syncthreads();

        #pragma unroll
        for (int kk = 0; kk < BK; ++kk) {
            float a[TM], b[TN];
            #pragma unroll
            for (int i = 0; i < TM; i++) a[i] = As[kk][ty * TM + i];
            #pragma unroll
            for (int j = 0; j < TN; j++) b[j] = Bs[kk][tx * TN + j];
            #pragma unroll
            for (int i = 0; i < TM; i++)
                #pragma unroll
                for (int j = 0; j < TN; j++)
                    acc[i][j] = fmaf(a[i], b[j], acc[i][j]);
        }
        __syncthreads();
    }

    #pragma unroll
    for (int i = 0; i < TM; i++) {
        float4* cp = (float4*)(C + (long long)(m0 + ty * TM + i) * N + n0 + tx * TN);
        cp[0] = make_float4(acc[i][0], acc[i][1], acc[i][2], acc[i][3]);
        cp[1] = make_float4(acc[i][4], acc[i][5], acc[i][6], acc[i][7]);
    }
}

// C[m,n] = sum_k A[m,k] * B[k,n]   (A:[M,K] row-major, B:[K,N] row-major)
// klim: truncate k-loop at m0+BM (valid because softmax zero-fills the
// intra-tile upper triangle).
__global__ __launch_bounds__(NT) void gemm_nn(
    const float* __restrict__ A, const float* __restrict__ B, float* __restrict__ C,
    int M, int N, int K,
    long long sA, long long sB, long long sC, int klim)
{
    const int m0 = blockIdx.y * BM;
    const int n0 = blockIdx.x * BN;

    A += (long long)blockIdx.z * sA;
    B += (long long)blockIdx.z * sB;
    C += (long long)blockIdx.z * sC;

    const int kmax = klim ? min(K, m0 + BM) : K;

    __shared__ float As[BK][BM + 4];
    __shared__ float Bs[BK][BN + 4];

    const int tid = threadIdx.x;
    const int ty = tid >> 4;
    const int tx = tid & 15;

    float acc[TM][TN];
    #pragma unroll
    for (int i = 0; i < TM; i++)
        #pragma unroll
        for (int j = 0; j < TN; j++) acc[i][j] = 0.f;

    for (int k0 = 0; k0 < kmax; k0 += BK) {
        #pragma unroll
        for (int l = 0; l < 2; ++l) {
            int v = tid + l * NT;           // 0..511
            // A tile: transpose (k contiguous in gmem)
            int r = v >> 2;
            int c = (v & 3) << 2;
            float4 a = *(const float4*)(A + (long long)(m0 + r) * K + k0 + c);
            As[c + 0][r] = a.x; As[c + 1][r] = a.y;
            As[c + 2][r] = a.z; As[c + 3][r] = a.w;
            // B tile: direct (n contiguous in gmem) — fully coalesced
            int kk = v >> 5;                // 0..15
            int nc = (v & 31) << 2;         // 0..124
            float4 b = *(const float4*)(B + (long long)(k0 + kk) * N + n0 + nc);
            *(float4*)&Bs[kk][nc] = b;
        }
        __syncthreads();

        #pragma unroll
        for (int kk = 0; kk < BK; ++kk) {
            float a[TM], b[TN];
            #pragma unroll
            for (int i = 0; i < TM; i++) a[i] = As[kk][ty * TM + i];
            #pragma unroll
            for (int j = 0; j < TN; j++) b[j] = Bs[kk][tx * TN + j];
            #pragma unroll
            for (int i = 0; i < TM; i++)
                #pragma unroll
                for (int j = 0; j < TN; j++)
                    acc[i][j] = fmaf(a[i], b[j], acc[i][j]);
        }
        __syncthreads();
    }

    #pragma unroll
    for (int i = 0; i < TM; i++) {
        float4* cp = (float4*)(C + (long long)(m0 + ty * TM + i) * N + n0 + tx * TN);
        cp[0] = make_float4(acc[i][0], acc[i][1], acc[i][2], acc[i][3]);
        cp[1] = make_float4(acc[i][4], acc[i][5], acc[i][6], acc[i][7]);
    }
}

// One block per (row q, batch b). Softmax over k <= q with scale 1/32,
// then zero-fill k in (q, next multiple of BM) so gemm_nn's truncated
// k-loop sees exact zeros for the masked region.
__global__ __launch_bounds__(256) void causal_softmax(float* __restrict__ S, int n)
{
    const int q = blockIdx.x;
    float* row = S + ((long long)blockIdx.y * n + q) * (long long)n;
    const int tid = threadIdx.x;
    const float scale = 0.03125f;  // 1/sqrt(1024)
    const int cnt = q + 1;

    float vals[8];
    float mx = -1e30f;
    int ni = 0;
    for (int k = tid; k < cnt; k += 256, ++ni) {
        vals[ni] = row[k] * scale;
        mx = fmaxf(mx, vals[ni]);
    }

    __shared__ float red[256];
    red[tid] = mx;
    __syncthreads();
    #pragma unroll
    for (int s = 128; s > 0; s >>= 1) {
        if (tid < s) red[tid] = fmaxf(red[tid], red[tid + s]);
        __syncthreads();
    }
    mx = red[0];
    __syncthreads();

    float sum = 0.f;
    #pragma unroll 8
    for (int i = 0; i < ni; ++i) {
        vals[i] = __expf(vals[i] - mx);
        sum += vals[i];
    }
    red[tid] = sum;
    __syncthreads();
    #pragma unroll
    for (int s = 128; s > 0; s >>= 1) {
        if (tid < s) red[tid] += red[tid + s];
        __syncthreads();
    }
    const float inv = 1.f / red[0];

    {
        int i = 0;
        for (int k = tid; k < cnt; k += 256, ++i) row[k] = vals[i] * inv;
    }
    // Zero the intra-tile masked tail: k in [cnt, ceil(cnt/BM)*BM)
    const int lim = ((q / BM) + 1) * BM;
    for (int k = cnt + tid; k < lim; k += 256) row[k] = 0.f;
}

extern "C" void kernel_launch(void* const* d_in, const int* in_sizes, int n_in,
                              void* d_out, int out_size)
{
    const float* x  = (const float*)d_in[0];
    const float* Wq = (const float*)d_in[1];
    const float* Wk = (const float*)d_in[2];
    const float* Wv = (const float*)d_in[3];
    float* out = (float*)d_out;

    float *Q, *K, *V, *Sc;
    cudaGetSymbolAddress((void**)&Q,  g_Q);
    cudaGetSymbolAddress((void**)&K,  g_K);
    cudaGetSymbolAddress((void**)&V,  g_V);
    cudaGetSymbolAddress((void**)&Sc, g_S);

    dim3 blk(NT);

    // QKV projections: [8192,1024] x [1024,1024]^T
    dim3 gqkv(P_ / BN, (B_ * S_) / BM, 1);
    gemm_nt<<<gqkv, blk>>>(x, Wq, Q, B_ * S_, P_, D_, 0, 0, 0, 0);
    gemm_nt<<<gqkv, blk>>>(x, Wk, K, B_ * S_, P_, D_, 0, 0, 0, 0);
    gemm_nt<<<gqkv, blk>>>(x, Wv, V, B_ * S_, P_, D_, 0, 0, 0, 0);

    // scores = Q @ K^T per batch, lower-triangular tiles only
    dim3 gsc(S_ / BN, S_ / BM, B_);
    gemm_nt<<<gsc, blk>>>(Q, K, Sc, S_, S_, P_,
                          (long long)S_ * P_, (long long)S_ * P_,
                          (long long)S_ * S_, 1);

    // causal softmax (+ zero-fill intra-tile upper triangle)
    causal_softmax<<<dim3(S_, B_), 256>>>(Sc, S_);

    // Z = weights @ V per batch, k-loop truncated to causal band
    dim3 gz(P_ / BN, S_ / BM, B_);
    gemm_nn<<<gz, blk>>>(Sc, V, out, S_, P_, S_,
                         (long long)S_ * S_, (long long)S_ * P_,
                         (long long)S_ * P_, 1);
}

// round 3
// speedup vs baseline: 3.3685x; 3.3685x over previous
#include <cuda_runtime.h>
#include <cstdint>

#define B_ 4
#define S_ 2048
#define D_ 1024
#define P_ 1024

#define BM 128
#define BN 128
#define BK 32
#define NT_ 256
#define BKP 36                      // padded row stride in floats (144B, 16B-aligned)
#define TILE_F (BM * BKP)           // 4608 floats per tile
#define STAGE_F (2 * TILE_F)        // A + B
#define SMEM_BYTES (2 * STAGE_F * 4)  // 2 stages = 73728 B

// Scratch (static device arrays; no dynamic allocation anywhere).
__device__ float g_Q [(size_t)B_ * S_ * P_];
__device__ float g_K [(size_t)B_ * S_ * P_];
__device__ float g_V [(size_t)B_ * S_ * P_];
__device__ float g_Vt[(size_t)B_ * S_ * P_];
__device__ float g_S [(size_t)B_ * S_ * S_];

__device__ __forceinline__ uint32_t smem_u32(const void* p) {
    uint32_t a;
    asm("{ .reg .u64 t; cvta.to.shared.u64 t, %1; cvt.u32.u64 %0, t; }" : "=r"(a) : "l"(p));
    return a;
}
__device__ __forceinline__ void cp16(uint32_t dst, const void* src) {
    asm volatile("cp.async.cg.shared.global [%0], [%1], 16;" :: "r"(dst), "l"(src));
}
#define CP_COMMIT() asm volatile("cp.async.commit_group;" ::: "memory")
#define CP_WAIT(n)  asm volatile("cp.async.wait_group %0;" :: "n"(n) : "memory")

__device__ __forceinline__ uint32_t f2tf(float f) {
    uint32_t r;
    asm("cvt.rna.tf32.f32 %0, %1;" : "=r"(r) : "f"(f));
    return r;
}
__device__ __forceinline__ void mma_tf32(float* c, const uint32_t* a, const uint32_t* b) {
    asm volatile(
        "mma.sync.aligned.m16n8k8.row.col.f32.tf32.tf32.f32 "
        "{%0,%1,%2,%3}, {%4,%5,%6,%7}, {%8,%9}, {%0,%1,%2,%3};"
        : "+f"(c[0]), "+f"(c[1]), "+f"(c[2]), "+f"(c[3])
        : "r"(a[0]), "r"(a[1]), "r"(a[2]), "r"(a[3]), "r"(b[0]), "r"(b[1]));
}

// C[m,n] = sum_k A[m,k] * B[n,k]; A:[M,K], B:[N,K], C:[M,N] row-major.
// causal: skip tiles with n0 > m0. klim: truncate k at m0+BM.
__global__ __launch_bounds__(NT_, 2) void gemm_nt_tc(
    const float* __restrict__ A, const float* __restrict__ B, float* __restrict__ C,
    int M, int N, int K, long long sA, long long sB, long long sC,
    int causal, int klim)
{
    extern __shared__ float sm[];
    const int m0 = blockIdx.y * BM;
    const int n0 = blockIdx.x * BN;
    if (causal && n0 > m0) return;

    A += (long long)blockIdx.z * sA;
    B += (long long)blockIdx.z * sB;
    C += (long long)blockIdx.z * sC;

    const int kmax = klim ? min(K, m0 + BM) : K;
    const int nchunk = kmax / BK;

    const int tid = threadIdx.x;
    const int wid = tid >> 5, lane = tid & 31;
    const int g = lane >> 2, tg = lane & 3;
    const int wm = (wid >> 2) * 64;     // warp m offset (2 rows of warps)
    const int wn = (wid & 3) * 32;      // warp n offset (4 cols of warps)

    const uint32_t sbase = smem_u32(sm);
    const float* Abase = A + (size_t)m0 * K;
    const float* Bbase = B + (size_t)n0 * K;

    float acc[4][4][4];
    #pragma unroll
    for (int i = 0; i < 4; i++)
        #pragma unroll
        for (int j = 0; j < 4; j++)
            #pragma unroll
            for (int r = 0; r < 4; r++) acc[i][j][r] = 0.f;

    // async-load chunk c into stage s
    auto load_stage = [&](int c, int s) {
        const uint32_t ab = sbase + (uint32_t)(s * STAGE_F) * 4u;
        const uint32_t bb = ab + TILE_F * 4u;
        const float* Ag = Abase + (size_t)c * BK;
        const float* Bg = Bbase + (size_t)c * BK;
        #pragma unroll
        for (int j = 0; j < 4; j++) {
            int idx = j * NT_ + tid;        // 0..1023
            int row = idx >> 3;             // 0..127
            int kc = (idx & 7) * 4;         // float offset 0,4,...,28
            uint32_t doff = (uint32_t)(row * BKP + kc) * 4u;
            cp16(ab + doff, Ag + (size_t)row * K + kc);
            cp16(bb + doff, Bg + (size_t)row * K + kc);
        }
    };

    load_stage(0, 0);
    CP_COMMIT();

    for (int i = 0; i < nchunk; i++) {
        const int s = i & 1;
        if (i + 1 < nchunk) {
            load_stage(i + 1, (i + 1) & 1);
            CP_COMMIT();
            CP_WAIT(1);                 // chunk i resident
        } else {
            CP_WAIT(0);
        }
        __syncthreads();

        const float* As = sm + s * STAGE_F + wm * BKP;
        const float* Bs = sm + s * STAGE_F + TILE_F + wn * BKP;

        #pragma unroll
        for (int kk = 0; kk < BK; kk += 8) {
            uint32_t af[4][4], bf[4][2];
            #pragma unroll
            for (int mt = 0; mt < 4; mt++) {
                const float* ap = As + (mt * 16 + g) * BKP + kk + tg;
                af[mt][0] = f2tf(ap[0]);
                af[mt][1] = f2tf(ap[8 * BKP]);
                af[mt][2] = f2tf(ap[4]);
                af[mt][3] = f2tf(ap[8 * BKP + 4]);
            }
            #pragma unroll
            for (int nt = 0; nt < 4; nt++) {
                const float* bp = Bs + (nt * 8 + g) * BKP + kk + tg;
                bf[nt][0] = f2tf(bp[0]);
                bf[nt][1] = f2tf(bp[4]);
            }
            #pragma unroll
            for (int mt = 0; mt < 4; mt++)
                #pragma unroll
                for (int nt = 0; nt < 4; nt++)
                    mma_tf32(acc[mt][nt], af[mt], bf[nt]);
        }
        __syncthreads();
    }

    // epilogue: direct float2 stores
    #pragma unroll
    for (int mt = 0; mt < 4; mt++) {
        #pragma unroll
        for (int nt = 0; nt < 4; nt++) {
            const int row = m0 + wm + mt * 16 + g;
            const int col = n0 + wn + nt * 8 + tg * 2;
            *(float2*)(C + (size_t)row * N + col) =
                make_float2(acc[mt][nt][0], acc[mt][nt][1]);
            *(float2*)(C + (size_t)(row + 8) * N + col) =
                make_float2(acc[mt][nt][2], acc[mt][nt][3]);
        }
    }
}

// ---------------- V transpose: Vt[b][p][s] = V[b][s][p] ----------------
__global__ __launch_bounds__(256) void transpose_sp(
    const float* __restrict__ V, float* __restrict__ Vt)
{
    __shared__ float t[32][33];
    const int b = blockIdx.z;
    const int s0 = blockIdx.x * 32, p0 = blockIdx.y * 32;
    const float* Vb = V + (size_t)b * S_ * P_;
    float* Vtb = Vt + (size_t)b * S_ * P_;
    const int x = threadIdx.x, y = threadIdx.y;   // 32 x 8
    #pragma unroll
    for (int i = 0; i < 32; i += 8)
        t[y + i][x] = Vb[(size_t)(s0 + y + i) * P_ + p0 + x];
    __syncthreads();
    #pragma unroll
    for (int i = 0; i < 32; i += 8)
        Vtb[(size_t)(p0 + y + i) * S_ + s0 + x] = t[x][y + i];
}

// ---------------- causal softmax (+ zero-fill to tile boundary) ----------------
__global__ __launch_bounds__(256) void causal_softmax(float* __restrict__ S, int n)
{
    const int q = blockIdx.x;
    float* row = S + ((long long)blockIdx.y * n + q) * (long long)n;
    const int tid = threadIdx.x;
    const float scale = 0.03125f;   // 1/sqrt(1024)
    const int cnt = q + 1;

    float vals[8];
    float mx = -1e30f;
    int ni = 0;
    for (int k = tid; k < cnt; k += 256, ++ni) {
        vals[ni] = row[k] * scale;
        mx = fmaxf(mx, vals[ni]);
    }

    __shared__ float red[256];
    red[tid] = mx;
    __syncthreads();
    #pragma unroll
    for (int s = 128; s > 0; s >>= 1) {
        if (tid < s) red[tid] = fmaxf(red[tid], red[tid + s]);
        __syncthreads();
    }
    mx = red[0];
    __syncthreads();

    float sum = 0.f;
    #pragma unroll 8
    for (int i = 0; i < ni; ++i) {
        vals[i] = __expf(vals[i] - mx);
        sum += vals[i];
    }
    red[tid] = sum;
    __syncthreads();
    #pragma unroll
    for (int s = 128; s > 0; s >>= 1) {
        if (tid < s) red[tid] += red[tid + s];
        __syncthreads();
    }
    const float inv = 1.f / red[0];

    {
        int i = 0;
        for (int k = tid; k < cnt; k += 256, ++i) row[k] = vals[i] * inv;
    }
    const int lim = ((q / BM) + 1) * BM;
    for (int k = cnt + tid; k < lim; k += 256) row[k] = 0.f;
}

// ---------------- launcher ----------------
extern "C" void kernel_launch(void* const* d_in, const int* in_sizes, int n_in,
                              void* d_out, int out_size)
{
    const float* x  = (const float*)d_in[0];
    const float* Wq = (const float*)d_in[1];
    const float* Wk = (const float*)d_in[2];
    const float* Wv = (const float*)d_in[3];
    float* out = (float*)d_out;

    float *Q, *K, *V, *Vt, *Sc;
    cudaGetSymbolAddress((void**)&Q,  g_Q);
    cudaGetSymbolAddress((void**)&K,  g_K);
    cudaGetSymbolAddress((void**)&V,  g_V);
    cudaGetSymbolAddress((void**)&Vt, g_Vt);
    cudaGetSymbolAddress((void**)&Sc, g_S);

    cudaFuncSetAttribute(gemm_nt_tc, cudaFuncAttributeMaxDynamicSharedMemorySize, SMEM_BYTES);

    dim3 blk(NT_);

    // QKV projections: [8192,1024] = x @ W^T
    dim3 gproj(P_ / BN, (B_ * S_) / BM, 1);
    gemm_nt_tc<<<gproj, blk, SMEM_BYTES>>>(x, Wq, Q, B_ * S_, P_, D_, 0, 0, 0, 0, 0);
    gemm_nt_tc<<<gproj, blk, SMEM_BYTES>>>(x, Wk, K, B_ * S_, P_, D_, 0, 0, 0, 0, 0);
    gemm_nt_tc<<<gproj, blk, SMEM_BYTES>>>(x, Wv, V, B_ * S_, P_, D_, 0, 0, 0, 0, 0);

    // V transpose for the NT-form Z gemm
    transpose_sp<<<dim3(S_ / 32, P_ / 32, B_), dim3(32, 8)>>>(V, Vt);

    // scores = Q @ K^T per batch (causal tile skip)
    dim3 gsc(S_ / BN, S_ / BM, B_);
    gemm_nt_tc<<<gsc, blk, SMEM_BYTES>>>(Q, K, Sc, S_, S_, P_,
                                         (long long)S_ * P_, (long long)S_ * P_,
                                         (long long)S_ * S_, 1, 0);

    // causal softmax + zero-fill
    causal_softmax<<<dim3(S_, B_), 256>>>(Sc, S_);

    // Z = weights @ V = weights @ Vt^T per batch, k truncated to causal band
    dim3 gz(P_ / BN, S_ / BM, B_);
    gemm_nt_tc<<<gz, blk, SMEM_BYTES>>>(Sc, Vt, out, S_, P_, S_,
                                        (long long)S_ * S_, (long long)S_ * P_,
                                        (long long)S_ * P_, 0, 1);
}

// round 4
// speedup vs baseline: 3.9692x; 1.1783x over previous
#include <cuda_runtime.h>
#include <cstdint>

#define B_ 4
#define S_ 2048
#define D_ 1024
#define P_ 1024

#define BM 128
#define BN 128
#define BK 32
#define NT_ 256
#define BKP 36                      // padded row stride in floats (144B)
#define TILE_F (BM * BKP)
#define STAGE_F (2 * TILE_F)
#define SMEM_BYTES (2 * STAGE_F * 4)  // 73728 B -> 2 CTAs/SM

// Scratch (static device arrays; no dynamic allocation anywhere).
__device__ float g_Q  [(size_t)B_ * S_ * P_];
__device__ float g_K  [(size_t)B_ * S_ * P_];
__device__ float g_V  [(size_t)B_ * S_ * P_];
__device__ float g_Vt [(size_t)B_ * S_ * P_];
__device__ float g_S  [(size_t)B_ * S_ * S_];
__device__ float g_xr [(size_t)B_ * S_ * D_];
__device__ float g_Wr [3][(size_t)P_ * D_];

__device__ __forceinline__ uint32_t smem_u32(const void* p) {
    uint32_t a;
    asm("{ .reg .u64 t; cvta.to.shared.u64 t, %1; cvt.u32.u64 %0, t; }" : "=r"(a) : "l"(p));
    return a;
}
__device__ __forceinline__ void cp16(uint32_t dst, const void* src) {
    asm volatile("cp.async.cg.shared.global [%0], [%1], 16;" :: "r"(dst), "l"(src));
}
#define CP_COMMIT() asm volatile("cp.async.commit_group;" ::: "memory")
#define CP_WAIT(n)  asm volatile("cp.async.wait_group %0;" :: "n"(n) : "memory")

__device__ __forceinline__ float f2tf(float f) {
    uint32_t r;
    asm("cvt.rna.tf32.f32 %0, %1;" : "=r"(r) : "f"(f));
    return __uint_as_float(r);
}
#define LDSM4(r0, r1, r2, r3, a)                                                  \
    asm volatile("ldmatrix.sync.aligned.m8n8.x4.shared.b16 {%0,%1,%2,%3}, [%4];"  \
        : "=r"(r0), "=r"(r1), "=r"(r2), "=r"(r3) : "r"(a))

__device__ __forceinline__ void mma_tf32(float* c, const uint32_t* a,
                                         uint32_t b0, uint32_t b1) {
    asm volatile(
        "mma.sync.aligned.m16n8k8.row.col.f32.tf32.tf32.f32 "
        "{%0,%1,%2,%3}, {%4,%5,%6,%7}, {%8,%9}, {%0,%1,%2,%3};"
        : "+f"(c[0]), "+f"(c[1]), "+f"(c[2]), "+f"(c[3])
        : "r"(a[0]), "r"(a[1]), "r"(a[2]), "r"(a[3]), "r"(b0), "r"(b1));
}

// C[m,n] = sum_k A[m,k] * B[n,k]; all operands pre-rounded to tf32.
// mode 0 (projections): z selects B0/B1/B2 -> C0/C1/C2, A shared.
// mode 1 (batched): A += z*sA, B = B0 + z*sB, C = C0 + z*sC.
__global__ __launch_bounds__(NT_, 2) void gemm_nt_tc(
    const float* __restrict__ A,
    const float* __restrict__ B0, const float* __restrict__ B1, const float* __restrict__ B2,
    float* __restrict__ C0, float* __restrict__ C1, float* __restrict__ C2,
    int M, int N, int K, long long sA, long long sB, long long sC,
    int mode, int causal, int klim, int round_out)
{
    extern __shared__ float sm[];
    const int m0 = blockIdx.y * BM;
    const int n0 = blockIdx.x * BN;
    if (causal && n0 > m0) return;

    const float* B;
    float* C;
    if (mode == 0) {
        B = (blockIdx.z == 0) ? B0 : (blockIdx.z == 1) ? B1 : B2;
        C = (blockIdx.z == 0) ? C0 : (blockIdx.z == 1) ? C1 : C2;
    } else {
        A += (long long)blockIdx.z * sA;
        B = B0 + (long long)blockIdx.z * sB;
        C = C0 + (long long)blockIdx.z * sC;
    }

    const int kmax = klim ? min(K, m0 + BM) : K;
    const int nchunk = kmax / BK;

    const int tid = threadIdx.x;
    const int wid = tid >> 5, lane = tid & 31;
    const int g = lane >> 2, tg = lane & 3;
    const int wm = (wid >> 2) * 64;
    const int wn = (wid & 3) * 32;

    const uint32_t sbase = smem_u32(sm);
    const float* Abase = A + (size_t)m0 * K;
    const float* Bbase = B + (size_t)n0 * K;

    // ldmatrix per-thread offsets (relative to stage base, bytes)
    uint32_t offA[4], offB[2];
    {
        const int rA = lane & 15;              // row within 16-row block
        const int cA = (lane >> 4) * 16;       // 0 or 16 bytes (4 f32)
        #pragma unroll
        for (int mt = 0; mt < 4; mt++)
            offA[mt] = (uint32_t)((wm + mt * 16 + rA) * BKP) * 4u + cA;
        const int rB = (lane & 7) + ((lane >> 4) << 3);   // row within 16
        const int cB = ((lane >> 3) & 1) * 16;
        #pragma unroll
        for (int gb = 0; gb < 2; gb++)
            offB[gb] = (uint32_t)(TILE_F * 4) +
                       (uint32_t)((wn + gb * 16 + rB) * BKP) * 4u + cB;
    }

    float acc[4][4][4];
    #pragma unroll
    for (int i = 0; i < 4; i++)
        #pragma unroll
        for (int j = 0; j < 4; j++)
            #pragma unroll
            for (int r = 0; r < 4; r++) acc[i][j][r] = 0.f;

    auto load_stage = [&](int c, int s) {
        const uint32_t ab = sbase + (uint32_t)(s * STAGE_F) * 4u;
        const uint32_t bb = ab + TILE_F * 4u;
        const float* Ag = Abase + (size_t)c * BK;
        const float* Bg = Bbase + (size_t)c * BK;
        #pragma unroll
        for (int j = 0; j < 4; j++) {
            int idx = j * NT_ + tid;
            int row = idx >> 3;
            int kc = (idx & 7) * 4;
            uint32_t doff = (uint32_t)(row * BKP + kc) * 4u;
            cp16(ab + doff, Ag + (size_t)row * K + kc);
            cp16(bb + doff, Bg + (size_t)row * K + kc);
        }
    };

    load_stage(0, 0);
    CP_COMMIT();

    for (int i = 0; i < nchunk; i++) {
        const int s = i & 1;
        if (i + 1 < nchunk) {
            load_stage(i + 1, (i + 1) & 1);
            CP_COMMIT();
            CP_WAIT(1);
        } else {
            CP_WAIT(0);
        }
        __syncthreads();

        const uint32_t stb = sbase + (uint32_t)(s * STAGE_F) * 4u;
        #pragma unroll
        for (int kk = 0; kk < 4; kk++) {      // 8 f32 of k per step = 32B
            const uint32_t ko = kk * 32u;
            uint32_t af[4][4], bf[2][4];
            #pragma unroll
            for (int mt = 0; mt < 4; mt++)
                LDSM4(af[mt][0], af[mt][1], af[mt][2], af[mt][3], stb + offA[mt] + ko);
            #pragma unroll
            for (int gb = 0; gb < 2; gb++)
                LDSM4(bf[gb][0], bf[gb][1], bf[gb][2], bf[gb][3], stb + offB[gb] + ko);
            #pragma unroll
            for (int mt = 0; mt < 4; mt++)
                #pragma unroll
                for (int nt = 0; nt < 4; nt++)
                    mma_tf32(acc[mt][nt], af[mt],
                             bf[nt >> 1][(nt & 1) * 2], bf[nt >> 1][(nt & 1) * 2 + 1]);
        }
        __syncthreads();
    }

    #pragma unroll
    for (int mt = 0; mt < 4; mt++) {
        #pragma unroll
        for (int nt = 0; nt < 4; nt++) {
            float v0 = acc[mt][nt][0], v1 = acc[mt][nt][1];
            float v2 = acc[mt][nt][2], v3 = acc[mt][nt][3];
            if (round_out) { v0 = f2tf(v0); v1 = f2tf(v1); v2 = f2tf(v2); v3 = f2tf(v3); }
            const int row = m0 + wm + mt * 16 + g;
            const int col = n0 + wn + nt * 8 + tg * 2;
            *(float2*)(C + (size_t)row * N + col) = make_float2(v0, v1);
            *(float2*)(C + (size_t)(row + 8) * N + col) = make_float2(v2, v3);
        }
    }
}

// ---------------- elementwise tf32 rounding ----------------
__global__ __launch_bounds__(256) void round_tf32(const float* __restrict__ in,
                                                  float* __restrict__ out, int n4)
{
    int i = blockIdx.x * 256 + threadIdx.x;
    if (i < n4) {
        float4 v = ((const float4*)in)[i];
        ((float4*)out)[i] = make_float4(f2tf(v.x), f2tf(v.y), f2tf(v.z), f2tf(v.w));
    }
}

// ---------------- V transpose: Vt[b][p][s] = V[b][s][p] ----------------
__global__ __launch_bounds__(256) void transpose_sp(
    const float* __restrict__ V, float* __restrict__ Vt)
{
    __shared__ float t[32][33];
    const int b = blockIdx.z;
    const int s0 = blockIdx.x * 32, p0 = blockIdx.y * 32;
    const float* Vb = V + (size_t)b * S_ * P_;
    float* Vtb = Vt + (size_t)b * S_ * P_;
    const int x = threadIdx.x, y = threadIdx.y;
    #pragma unroll
    for (int i = 0; i < 32; i += 8)
        t[y + i][x] = Vb[(size_t)(s0 + y + i) * P_ + p0 + x];
    __syncthreads();
    #pragma unroll
    for (int i = 0; i < 32; i += 8)
        Vtb[(size_t)(p0 + y + i) * S_ + s0 + x] = t[x][y + i];
}

// ---------------- causal softmax (rounds weights to tf32, zero-fills) ----------------
__global__ __launch_bounds__(256) void causal_softmax(float* __restrict__ S, int n)
{
    const int q = blockIdx.x;
    float* row = S + ((long long)blockIdx.y * n + q) * (long long)n;
    const int tid = threadIdx.x;
    const int wid = tid >> 5, lane = tid & 31;
    const float scale = 0.03125f;   // 1/sqrt(1024)
    const int cnt = q + 1;

    float vals[8];
    float mx = -1e30f;
    int ni = 0;
    for (int k = tid; k < cnt; k += 256, ++ni) {
        vals[ni] = row[k] * scale;
        mx = fmaxf(mx, vals[ni]);
    }

    __shared__ float red[8];
    #pragma unroll
    for (int o = 16; o > 0; o >>= 1) mx = fmaxf(mx, __shfl_xor_sync(0xffffffffu, mx, o));
    if (lane == 0) red[wid] = mx;
    __syncthreads();
    mx = red[0];
    #pragma unroll
    for (int w = 1; w < 8; w++) mx = fmaxf(mx, red[w]);
    __syncthreads();

    float sum = 0.f;
    #pragma unroll 8
    for (int i = 0; i < ni; ++i) {
        vals[i] = __expf(vals[i] - mx);
        sum += vals[i];
    }
    #pragma unroll
    for (int o = 16; o > 0; o >>= 1) sum += __shfl_xor_sync(0xffffffffu, sum, o);
    if (lane == 0) red[wid] = sum;
    __syncthreads();
    sum = red[0];
    #pragma unroll
    for (int w = 1; w < 8; w++) sum += red[w];
    const float inv = 1.f / sum;

    {
        int i = 0;
        for (int k = tid; k < cnt; k += 256, ++i) row[k] = f2tf(vals[i] * inv);
    }
    const int lim = ((q / BM) + 1) * BM;
    for (int k = cnt + tid; k < lim; k += 256) row[k] = 0.f;
}

// ---------------- launcher ----------------
extern "C" void kernel_launch(void* const* d_in, const int* in_sizes, int n_in,
                              void* d_out, int out_size)
{
    const float* x  = (const float*)d_in[0];
    const float* Wq = (const float*)d_in[1];
    const float* Wk = (const float*)d_in[2];
    const float* Wv = (const float*)d_in[3];
    float* out = (float*)d_out;

    float *Q, *K, *V, *Vt, *Sc, *xr, *Wr;
    cudaGetSymbolAddress((void**)&Q,  g_Q);
    cudaGetSymbolAddress((void**)&K,  g_K);
    cudaGetSymbolAddress((void**)&V,  g_V);
    cudaGetSymbolAddress((void**)&Vt, g_Vt);
    cudaGetSymbolAddress((void**)&Sc, g_S);
    cudaGetSymbolAddress((void**)&xr, g_xr);
    cudaGetSymbolAddress((void**)&Wr, g_Wr);
    float* Wqr = Wr;
    float* Wkr = Wr + (size_t)P_ * D_;
    float* Wvr = Wr + 2 * (size_t)P_ * D_;

    cudaFuncSetAttribute(gemm_nt_tc, cudaFuncAttributeMaxDynamicSharedMemorySize, SMEM_BYTES);

    // pre-round inputs to tf32 (rna) once
    const int nx4 = (B_ * S_ * D_) / 4, nw4 = (P_ * D_) / 4;
    round_tf32<<<(nx4 + 255) / 256, 256>>>(x, xr, nx4);
    round_tf32<<<(nw4 + 255) / 256, 256>>>(Wq, Wqr, nw4);
    round_tf32<<<(nw4 + 255) / 256, 256>>>(Wk, Wkr, nw4);
    round_tf32<<<(nw4 + 255) / 256, 256>>>(Wv, Wvr, nw4);

    dim3 blk(NT_);

    // merged QKV projections (z selects weight/output); outputs tf32-rounded
    dim3 gproj(P_ / BN, (B_ * S_) / BM, 3);
    gemm_nt_tc<<<gproj, blk, SMEM_BYTES>>>(xr, Wqr, Wkr, Wvr, Q, K, V,
                                           B_ * S_, P_, D_, 0, 0, 0, 0, 0, 0, 1);

    // V transpose for the NT-form Z gemm
    transpose_sp<<<dim3(S_ / 32, P_ / 32, B_), dim3(32, 8)>>>(V, Vt);

    // scores = Q @ K^T per batch (causal tile skip); keep full fp32
    dim3 gsc(S_ / BN, S_ / BM, B_);
    gemm_nt_tc<<<gsc, blk, SMEM_BYTES>>>(Q, K, nullptr, nullptr, Sc, nullptr, nullptr,
                                         S_, S_, P_,
                                         (long long)S_ * P_, (long long)S_ * P_,
                                         (long long)S_ * S_, 1, 1, 0, 0);

    // causal softmax (+ tf32 rounding of weights, zero-fill)
    causal_softmax<<<dim3(S_, B_), 256>>>(Sc, S_);

    // Z = weights @ Vt^T per batch, k truncated to causal band; full fp32 out
    dim3 gz(P_ / BN, S_ / BM, B_);
    gemm_nt_tc<<<gz, blk, SMEM_BYTES>>>(Sc, Vt, nullptr, nullptr, out, nullptr, nullptr,
                                        S_, P_, S_,
                                        (long long)S_ * S_, (long long)S_ * P_,
                                        (long long)S_ * P_, 1, 0, 1, 0);
}

// round 5
// speedup vs baseline: 4.6012x; 1.1592x over previous
#include <cuda_runtime.h>
#include <cuda_fp16.h>
#include <cstdint>

#define B_ 4
#define S_ 2048
#define D_ 1024
#define P_ 1024

#define BM 128
#define BN 128
#define BK 64                        // halves of k per chunk (128B/row)
#define NT_ 256
#define BKH 72                       // padded row stride in halves (144B)
#define TILE_H (BM * BKH)            // halves per tile
#define STAGE_BYTES (2 * TILE_H * 2) // A+B tiles
#define SMEM_BYTES (2 * STAGE_BYTES) // 2 stages = 73728 B -> 2 CTAs/SM

// Scratch (static device arrays; no dynamic allocation anywhere).
__device__ __half g_Q  [(size_t)B_ * S_ * P_];
__device__ __half g_K  [(size_t)B_ * S_ * P_];
__device__ __half g_V  [(size_t)B_ * S_ * P_];
__device__ __half g_Vt [(size_t)B_ * S_ * P_];
__device__ __half g_W  [(size_t)B_ * S_ * S_];   // softmax weights (half)
__device__ float  g_S  [(size_t)B_ * S_ * S_];   // raw scores (fp32)
__device__ __half g_xh [(size_t)B_ * S_ * D_];
__device__ __half g_Wh [3][(size_t)P_ * D_];

__device__ __forceinline__ uint32_t smem_u32(const void* p) {
    uint32_t a;
    asm("{ .reg .u64 t; cvta.to.shared.u64 t, %1; cvt.u32.u64 %0, t; }" : "=r"(a) : "l"(p));
    return a;
}
__device__ __forceinline__ void cp16(uint32_t dst, const void* src) {
    asm volatile("cp.async.cg.shared.global [%0], [%1], 16;" :: "r"(dst), "l"(src));
}
#define CP_COMMIT() asm volatile("cp.async.commit_group;" ::: "memory")
#define CP_WAIT(n)  asm volatile("cp.async.wait_group %0;" :: "n"(n) : "memory")

#define LDSM4(r0, r1, r2, r3, a)                                                  \
    asm volatile("ldmatrix.sync.aligned.m8n8.x4.shared.b16 {%0,%1,%2,%3}, [%4];"  \
        : "=r"(r0), "=r"(r1), "=r"(r2), "=r"(r3) : "r"(a))

__device__ __forceinline__ void mma_f16(float* c, const uint32_t* a,
                                        uint32_t b0, uint32_t b1) {
    asm volatile(
        "mma.sync.aligned.m16n8k16.row.col.f32.f16.f16.f32 "
        "{%0,%1,%2,%3}, {%4,%5,%6,%7}, {%8,%9}, {%0,%1,%2,%3};"
        : "+f"(c[0]), "+f"(c[1]), "+f"(c[2]), "+f"(c[3])
        : "r"(a[0]), "r"(a[1]), "r"(a[2]), "r"(a[3]), "r"(b0), "r"(b1));
}

// C[m,n] = sum_k A[m,k] * B[n,k]; A,B half row-major; C fp32 or fp16.
// mode 0 (projections): z selects B0/B1/B2 -> Ch0/Ch1/Ch2 (half out).
// mode 1: A += z*sA, B = B0 + z*sB, C = z-strided; out_half selects type.
__global__ __launch_bounds__(NT_, 2) void gemm_nt_h(
    const __half* __restrict__ A,
    const __half* __restrict__ B0, const __half* __restrict__ B1, const __half* __restrict__ B2,
    float* __restrict__ Cf, __half* __restrict__ Ch0, __half* __restrict__ Ch1, __half* __restrict__ Ch2,
    int M, int N, int K, long long sA, long long sB, long long sC,
    int mode, int causal, int klim, int out_half)
{
    extern __shared__ char smraw[];
    const int m0 = blockIdx.y * BM;
    const int n0 = blockIdx.x * BN;
    if (causal && n0 > m0) return;

    const __half* B;
    float* Cf_ = Cf;
    __half* Ch_ = Ch0;
    if (mode == 0) {
        B   = (blockIdx.z == 0) ? B0 : (blockIdx.z == 1) ? B1 : B2;
        Ch_ = (blockIdx.z == 0) ? Ch0 : (blockIdx.z == 1) ? Ch1 : Ch2;
    } else {
        A += (long long)blockIdx.z * sA;
        B = B0 + (long long)blockIdx.z * sB;
        if (out_half) Ch_ = Ch0 + (long long)blockIdx.z * sC;
        else          Cf_ = Cf  + (long long)blockIdx.z * sC;
    }

    const int kmax = klim ? min(K, m0 + BM) : K;
    const int nchunk = kmax / BK;

    const int tid = threadIdx.x;
    const int wid = tid >> 5, lane = tid & 31;
    const int g = lane >> 2, tg = lane & 3;
    const int wm = (wid >> 2) * 64;
    const int wn = (wid & 3) * 32;

    const uint32_t sbase = smem_u32(smraw);
    const __half* Abase = A + (size_t)m0 * K;
    const __half* Bbase = B + (size_t)n0 * K;

    // ldmatrix per-thread offsets (bytes, relative to stage base)
    uint32_t offA[4], offB[2];
    {
        const int rA = lane & 15;
        const int cA = (lane >> 4) * 16;
        #pragma unroll
        for (int mt = 0; mt < 4; mt++)
            offA[mt] = (uint32_t)((wm + mt * 16 + rA) * BKH) * 2u + cA;
        const int rB = (lane & 7) + ((lane >> 4) << 3);
        const int cB = ((lane >> 3) & 1) * 16;
        #pragma unroll
        for (int gb = 0; gb < 2; gb++)
            offB[gb] = (uint32_t)(TILE_H * 2) +
                       (uint32_t)((wn + gb * 16 + rB) * BKH) * 2u + cB;
    }

    float acc[4][4][4];
    #pragma unroll
    for (int i = 0; i < 4; i++)
        #pragma unroll
        for (int j = 0; j < 4; j++)
            #pragma unroll
            for (int r = 0; r < 4; r++) acc[i][j][r] = 0.f;

    auto load_stage = [&](int c, int s) {
        const uint32_t ab = sbase + (uint32_t)s * STAGE_BYTES;
        const uint32_t bb = ab + TILE_H * 2u;
        const __half* Ag = Abase + (size_t)c * BK;
        const __half* Bg = Bbase + (size_t)c * BK;
        #pragma unroll
        for (int j = 0; j < 4; j++) {
            int idx = j * NT_ + tid;        // 0..1023
            int row = idx >> 3;             // 0..127
            int kc = (idx & 7) * 8;         // halves: 0,8,...,56
            uint32_t doff = (uint32_t)(row * BKH + kc) * 2u;
            cp16(ab + doff, Ag + (size_t)row * K + kc);
            cp16(bb + doff, Bg + (size_t)row * K + kc);
        }
    };

    load_stage(0, 0);
    CP_COMMIT();

    for (int i = 0; i < nchunk; i++) {
        const int s = i & 1;
        if (i + 1 < nchunk) {
            load_stage(i + 1, (i + 1) & 1);
            CP_COMMIT();
            CP_WAIT(1);
        } else {
            CP_WAIT(0);
        }
        __syncthreads();

        const uint32_t stb = sbase + (uint32_t)s * STAGE_BYTES;
        #pragma unroll
        for (int kk = 0; kk < 4; kk++) {        // 16 halves of k per step = 32B
            const uint32_t ko = kk * 32u;
            uint32_t af[4][4], bf[2][4];
            #pragma unroll
            for (int mt = 0; mt < 4; mt++)
                LDSM4(af[mt][0], af[mt][1], af[mt][2], af[mt][3], stb + offA[mt] + ko);
            #pragma unroll
            for (int gb = 0; gb < 2; gb++)
                LDSM4(bf[gb][0], bf[gb][1], bf[gb][2], bf[gb][3], stb + offB[gb] + ko);
            #pragma unroll
            for (int mt = 0; mt < 4; mt++)
                #pragma unroll
                for (int nt = 0; nt < 4; nt++)
                    mma_f16(acc[mt][nt], af[mt],
                            bf[nt >> 1][(nt & 1) * 2], bf[nt >> 1][(nt & 1) * 2 + 1]);
        }
        __syncthreads();
    }

    #pragma unroll
    for (int mt = 0; mt < 4; mt++) {
        #pragma unroll
        for (int nt = 0; nt < 4; nt++) {
            const int row = m0 + wm + mt * 16 + g;
            const int col = n0 + wn + nt * 8 + tg * 2;
            if (out_half) {
                *(__half2*)(Ch_ + (size_t)row * N + col) =
                    __floats2half2_rn(acc[mt][nt][0], acc[mt][nt][1]);
                *(__half2*)(Ch_ + (size_t)(row + 8) * N + col) =
                    __floats2half2_rn(acc[mt][nt][2], acc[mt][nt][3]);
            } else {
                *(float2*)(Cf_ + (size_t)row * N + col) =
                    make_float2(acc[mt][nt][0], acc[mt][nt][1]);
                *(float2*)(Cf_ + (size_t)(row + 8) * N + col) =
                    make_float2(acc[mt][nt][2], acc[mt][nt][3]);
            }
        }
    }
}

// ---------------- fp32 -> fp16 conversion ----------------
__global__ __launch_bounds__(256) void to_half(const float* __restrict__ in,
                                               __half* __restrict__ out, int n4)
{
    int i = blockIdx.x * 256 + threadIdx.x;
    if (i < n4) {
        float4 v = ((const float4*)in)[i];
        __half2 h0 = __floats2half2_rn(v.x, v.y);
        __half2 h1 = __floats2half2_rn(v.z, v.w);
        ((uint2*)out)[i] = make_uint2(*(uint32_t*)&h0, *(uint32_t*)&h1);
    }
}

// ---------------- V transpose (half): Vt[b][p][s] = V[b][s][p] ----------------
__global__ __launch_bounds__(256) void transpose_sp(
    const __half* __restrict__ V, __half* __restrict__ Vt)
{
    __shared__ __half t[32][34];
    const int b = blockIdx.z;
    const int s0 = blockIdx.x * 32, p0 = blockIdx.y * 32;
    const __half* Vb = V + (size_t)b * S_ * P_;
    __half* Vtb = Vt + (size_t)b * S_ * P_;
    const int x = threadIdx.x, y = threadIdx.y;
    #pragma unroll
    for (int i = 0; i < 32; i += 8)
        t[y + i][x] = Vb[(size_t)(s0 + y + i) * P_ + p0 + x];
    __syncthreads();
    #pragma unroll
    for (int i = 0; i < 32; i += 8)
        Vtb[(size_t)(p0 + y + i) * S_ + s0 + x] = t[x][y + i];
}

// ---------------- causal softmax: fp32 scores -> half weights ----------------
__global__ __launch_bounds__(256) void causal_softmax(
    const float* __restrict__ S, __half* __restrict__ W, int n)
{
    const int q = blockIdx.x;
    const float* row = S + ((long long)blockIdx.y * n + q) * (long long)n;
    __half* wrow = W + ((long long)blockIdx.y * n + q) * (long long)n;
    const int tid = threadIdx.x;
    const int wid = tid >> 5, lane = tid & 31;
    const float scale = 0.03125f;   // 1/sqrt(1024)
    const int cnt = q + 1;

    float vals[8];
    float mx = -1e30f;
    int ni = 0;
    for (int k = tid; k < cnt; k += 256, ++ni) {
        vals[ni] = row[k] * scale;
        mx = fmaxf(mx, vals[ni]);
    }

    __shared__ float red[8];
    #pragma unroll
    for (int o = 16; o > 0; o >>= 1) mx = fmaxf(mx, __shfl_xor_sync(0xffffffffu, mx, o));
    if (lane == 0) red[wid] = mx;
    __syncthreads();
    mx = red[0];
    #pragma unroll
    for (int w = 1; w < 8; w++) mx = fmaxf(mx, red[w]);
    __syncthreads();

    float sum = 0.f;
    #pragma unroll 8
    for (int i = 0; i < ni; ++i) {
        vals[i] = __expf(vals[i] - mx);
        sum += vals[i];
    }
    #pragma unroll
    for (int o = 16; o > 0; o >>= 1) sum += __shfl_xor_sync(0xffffffffu, sum, o);
    if (lane == 0) red[wid] = sum;
    __syncthreads();
    sum = red[0];
    #pragma unroll
    for (int w = 1; w < 8; w++) sum += red[w];
    const float inv = 1.f / sum;

    {
        int i = 0;
        for (int k = tid; k < cnt; k += 256, ++i)
            wrow[k] = __float2half_rn(vals[i] * inv);
    }
    const int lim = ((q / BM) + 1) * BM;
    for (int k = cnt + tid; k < lim; k += 256) wrow[k] = __float2half_rn(0.f);
}

// ---------------- launcher ----------------
extern "C" void kernel_launch(void* const* d_in, const int* in_sizes, int n_in,
                              void* d_out, int out_size)
{
    const float* x  = (const float*)d_in[0];
    const float* Wq = (const float*)d_in[1];
    const float* Wk = (const float*)d_in[2];
    const float* Wv = (const float*)d_in[3];
    float* out = (float*)d_out;

    __half *Q, *K, *V, *Vt, *Wgt, *xh, *Wh;
    float *Sc;
    cudaGetSymbolAddress((void**)&Q,   g_Q);
    cudaGetSymbolAddress((void**)&K,   g_K);
    cudaGetSymbolAddress((void**)&V,   g_V);
    cudaGetSymbolAddress((void**)&Vt,  g_Vt);
    cudaGetSymbolAddress((void**)&Wgt, g_W);
    cudaGetSymbolAddress((void**)&Sc,  g_S);
    cudaGetSymbolAddress((void**)&xh,  g_xh);
    cudaGetSymbolAddress((void**)&Wh,  g_Wh);
    __half* Wqh = Wh;
    __half* Wkh = Wh + (size_t)P_ * D_;
    __half* Wvh = Wh + 2 * (size_t)P_ * D_;

    cudaFuncSetAttribute(gemm_nt_h, cudaFuncAttributeMaxDynamicSharedMemorySize, SMEM_BYTES);

    // convert inputs to fp16 once
    const int nx4 = (B_ * S_ * D_) / 4, nw4 = (P_ * D_) / 4;
    to_half<<<(nx4 + 255) / 256, 256>>>(x, xh, nx4);
    to_half<<<(nw4 + 255) / 256, 256>>>(Wq, Wqh, nw4);
    to_half<<<(nw4 + 255) / 256, 256>>>(Wk, Wkh, nw4);
    to_half<<<(nw4 + 255) / 256, 256>>>(Wv, Wvh, nw4);

    dim3 blk(NT_);

    // merged QKV projections (z selects weight/output), half outputs
    dim3 gproj(P_ / BN, (B_ * S_) / BM, 3);
    gemm_nt_h<<<gproj, blk, SMEM_BYTES>>>(xh, Wqh, Wkh, Wvh,
                                          nullptr, Q, K, V,
                                          B_ * S_, P_, D_, 0, 0, 0, 0, 0, 0, 1);

    // V transpose for the NT-form Z gemm
    transpose_sp<<<dim3(S_ / 32, P_ / 32, B_), dim3(32, 8)>>>(V, Vt);

    // scores = Q @ K^T per batch (causal tile skip), fp32 out
    dim3 gsc(S_ / BN, S_ / BM, B_);
    gemm_nt_h<<<gsc, blk, SMEM_BYTES>>>(Q, K, nullptr, nullptr,
                                        Sc, nullptr, nullptr, nullptr,
                                        S_, S_, P_,
                                        (long long)S_ * P_, (long long)S_ * P_,
                                        (long long)S_ * S_, 1, 1, 0, 0);

    // causal softmax -> half weights (+ zero-fill to tile boundary)
    causal_softmax<<<dim3(S_, B_), 256>>>(Sc, Wgt, S_);

    // Z = weights @ Vt^T per batch, k truncated to causal band, fp32 out
    dim3 gz(P_ / BN, S_ / BM, B_);
    gemm_nt_h<<<gz, blk, SMEM_BYTES>>>(Wgt, Vt, nullptr, nullptr,
                                       out, nullptr, nullptr, nullptr,
                                       S_, P_, S_,
                                       (long long)S_ * S_, (long long)S_ * P_,
                                       (long long)S_ * P_, 1, 0, 1, 0);
}

// round 6
// speedup vs baseline: 4.6623x; 1.0133x over previous
#include <cuda_runtime.h>
#include <cuda_fp16.h>
#include <cstdint>

#define B_ 4
#define S_ 2048
#define D_ 1024
#define P_ 1024

#define BM 128
#define BN 128
#define BK 64                        // halves of k per chunk (128B/row)
#define NT_ 256
#define NSTAGE 3
#define BKH 72                       // padded row stride in halves (144B)
#define TILE_H (BM * BKH)
#define STAGE_BYTES (2 * TILE_H * 2) // A+B tiles = 36864
#define SMEM_BYTES (NSTAGE * STAGE_BYTES)  // 110592 -> 2 CTAs/SM

#define NX4 ((B_ * S_ * D_) / 4)     // float4 count of x
#define NW4 ((P_ * D_) / 4)          // float4 count of one W

// Scratch (static device arrays; no dynamic allocation anywhere).
__device__ __half g_Q  [(size_t)B_ * S_ * P_];
__device__ __half g_K  [(size_t)B_ * S_ * P_];
__device__ __half g_V  [(size_t)B_ * S_ * P_];
__device__ __half g_Vt [(size_t)B_ * S_ * P_];
__device__ __half g_W  [(size_t)B_ * S_ * S_];   // softmax weights (half)
__device__ float  g_S  [(size_t)B_ * S_ * S_];   // raw scores (fp32)
__device__ __half g_xh [(size_t)B_ * S_ * D_];
__device__ __half g_Wh [3][(size_t)P_ * D_];

__device__ __forceinline__ uint32_t smem_u32(const void* p) {
    uint32_t a;
    asm("{ .reg .u64 t; cvta.to.shared.u64 t, %1; cvt.u32.u64 %0, t; }" : "=r"(a) : "l"(p));
    return a;
}
__device__ __forceinline__ void cp16(uint32_t dst, const void* src) {
    asm volatile("cp.async.cg.shared.global [%0], [%1], 16;" :: "r"(dst), "l"(src));
}
#define CP_COMMIT() asm volatile("cp.async.commit_group;" ::: "memory")
#define CP_WAIT(n)  asm volatile("cp.async.wait_group %0;" :: "n"(n) : "memory")

#define LDSM4(r0, r1, r2, r3, a)                                                  \
    asm volatile("ldmatrix.sync.aligned.m8n8.x4.shared.b16 {%0,%1,%2,%3}, [%4];"  \
        : "=r"(r0), "=r"(r1), "=r"(r2), "=r"(r3) : "r"(a))

__device__ __forceinline__ void mma_f16(float* c, const uint32_t* a,
                                        uint32_t b0, uint32_t b1) {
    asm volatile(
        "mma.sync.aligned.m16n8k16.row.col.f32.f16.f16.f32 "
        "{%0,%1,%2,%3}, {%4,%5,%6,%7}, {%8,%9}, {%0,%1,%2,%3};"
        : "+f"(c[0]), "+f"(c[1]), "+f"(c[2]), "+f"(c[3])
        : "r"(a[0]), "r"(a[1]), "r"(a[2]), "r"(a[3]), "r"(b0), "r"(b1));
}

// C[m,n] = sum_k A[m,k] * B[n,k]; A,B half row-major; C fp32 or fp16.
// mode 0 (projections): z selects B0/B1/B2 -> Ch0/Ch1/Ch2 (half out).
// mode 1: A += z*sA, B = B0 + z*sB, C = z-strided; out_half selects type.
__global__ __launch_bounds__(NT_, 2) void gemm_nt_h(
    const __half* __restrict__ A,
    const __half* __restrict__ B0, const __half* __restrict__ B1, const __half* __restrict__ B2,
    float* __restrict__ Cf, __half* __restrict__ Ch0, __half* __restrict__ Ch1, __half* __restrict__ Ch2,
    int M, int N, int K, long long sA, long long sB, long long sC,
    int mode, int causal, int klim, int out_half)
{
    extern __shared__ char smraw[];
    const int m0 = blockIdx.y * BM;
    const int n0 = blockIdx.x * BN;
    if (causal && n0 > m0) return;

    const __half* B;
    float* Cf_ = Cf;
    __half* Ch_ = Ch0;
    if (mode == 0) {
        B   = (blockIdx.z == 0) ? B0 : (blockIdx.z == 1) ? B1 : B2;
        Ch_ = (blockIdx.z == 0) ? Ch0 : (blockIdx.z == 1) ? Ch1 : Ch2;
    } else {
        A += (long long)blockIdx.z * sA;
        B = B0 + (long long)blockIdx.z * sB;
        if (out_half) Ch_ = Ch0 + (long long)blockIdx.z * sC;
        else          Cf_ = Cf  + (long long)blockIdx.z * sC;
    }

    const int kmax = klim ? min(K, m0 + BM) : K;
    const int nchunk = kmax / BK;        // always >= 2 here

    const int tid = threadIdx.x;
    const int wid = tid >> 5, lane = tid & 31;
    const int g = lane >> 2, tg = lane & 3;
    const int wm = (wid >> 2) * 64;
    const int wn = (wid & 3) * 32;

    const uint32_t sbase = smem_u32(smraw);
    const __half* Abase = A + (size_t)m0 * K;
    const __half* Bbase = B + (size_t)n0 * K;

    // ldmatrix per-thread offsets (bytes, relative to stage base)
    uint32_t offA[4], offB[2];
    {
        const int rA = lane & 15;
        const int cA = (lane >> 4) * 16;
        #pragma unroll
        for (int mt = 0; mt < 4; mt++)
            offA[mt] = (uint32_t)((wm + mt * 16 + rA) * BKH) * 2u + cA;
        const int rB = (lane & 7) + ((lane >> 4) << 3);
        const int cB = ((lane >> 3) & 1) * 16;
        #pragma unroll
        for (int gb = 0; gb < 2; gb++)
            offB[gb] = (uint32_t)(TILE_H * 2) +
                       (uint32_t)((wn + gb * 16 + rB) * BKH) * 2u + cB;
    }

    float acc[4][4][4];
    #pragma unroll
    for (int i = 0; i < 4; i++)
        #pragma unroll
        for (int j = 0; j < 4; j++)
            #pragma unroll
            for (int r = 0; r < 4; r++) acc[i][j][r] = 0.f;

    auto load_stage = [&](int c, int s) {
        const uint32_t ab = sbase + (uint32_t)s * STAGE_BYTES;
        const uint32_t bb = ab + TILE_H * 2u;
        const __half* Ag = Abase + (size_t)c * BK;
        const __half* Bg = Bbase + (size_t)c * BK;
        #pragma unroll
        for (int j = 0; j < 4; j++) {
            int idx = j * NT_ + tid;        // 0..1023
            int row = idx >> 3;             // 0..127
            int kc = (idx & 7) * 8;         // halves: 0,8,...,56
            uint32_t doff = (uint32_t)(row * BKH + kc) * 2u;
            cp16(ab + doff, Ag + (size_t)row * K + kc);
            cp16(bb + doff, Bg + (size_t)row * K + kc);
        }
    };

    // prologue: stages 0,1 in flight (nchunk >= 2 always)
    load_stage(0, 0);
    CP_COMMIT();
    load_stage(1, 1);
    CP_COMMIT();

    int sc = 0;                          // stage of chunk i
    for (int i = 0; i < nchunk; i++) {
        CP_WAIT(1);                      // chunk i resident (this thread)
        __syncthreads();                 // visibility + stage-recycle safety

        const int c2 = i + 2;
        if (c2 < nchunk) {
            int s2 = c2 - ((c2 >= NSTAGE) ? ((c2 >= 2 * NSTAGE) ? 2 * NSTAGE : NSTAGE) : 0);
            // cheap c2 % 3 for small range is fine, but keep exact mod:
            s2 = c2 % NSTAGE;
            load_stage(c2, s2);
        }
        CP_COMMIT();                     // commit (possibly empty) group

        const uint32_t stb = sbase + (uint32_t)sc * STAGE_BYTES;
        #pragma unroll
        for (int kk = 0; kk < 4; kk++) {        // 16 halves of k per step
            const uint32_t ko = kk * 32u;
            uint32_t af[4][4], bf[2][4];
            #pragma unroll
            for (int mt = 0; mt < 4; mt++)
                LDSM4(af[mt][0], af[mt][1], af[mt][2], af[mt][3], stb + offA[mt] + ko);
            #pragma unroll
            for (int gb = 0; gb < 2; gb++)
                LDSM4(bf[gb][0], bf[gb][1], bf[gb][2], bf[gb][3], stb + offB[gb] + ko);
            #pragma unroll
            for (int mt = 0; mt < 4; mt++)
                #pragma unroll
                for (int nt = 0; nt < 4; nt++)
                    mma_f16(acc[mt][nt], af[mt],
                            bf[nt >> 1][(nt & 1) * 2], bf[nt >> 1][(nt & 1) * 2 + 1]);
        }
        if (++sc == NSTAGE) sc = 0;
    }

    #pragma unroll
    for (int mt = 0; mt < 4; mt++) {
        #pragma unroll
        for (int nt = 0; nt < 4; nt++) {
            const int row = m0 + wm + mt * 16 + g;
            const int col = n0 + wn + nt * 8 + tg * 2;
            if (out_half) {
                *(__half2*)(Ch_ + (size_t)row * N + col) =
                    __floats2half2_rn(acc[mt][nt][0], acc[mt][nt][1]);
                *(__half2*)(Ch_ + (size_t)(row + 8) * N + col) =
                    __floats2half2_rn(acc[mt][nt][2], acc[mt][nt][3]);
            } else {
                *(float2*)(Cf_ + (size_t)row * N + col) =
                    make_float2(acc[mt][nt][0], acc[mt][nt][1]);
                *(float2*)(Cf_ + (size_t)(row + 8) * N + col) =
                    make_float2(acc[mt][nt][2], acc[mt][nt][3]);
            }
        }
    }
}

// ---------------- fp32 -> fp16 conversion, all 4 tensors in one launch ----------------
__global__ __launch_bounds__(256) void to_half_all(
    const float* __restrict__ x,  __half* __restrict__ xh,
    const float* __restrict__ w0, const float* __restrict__ w1, const float* __restrict__ w2,
    __half* __restrict__ wh)     // wh = base of g_Wh[3]
{
    int i = blockIdx.x * 256 + threadIdx.x;
    const float* src;
    __half* dst;
    int off;
    if (i < NX4) { src = x; dst = xh; off = i; }
    else {
        int j = i - NX4;
        int w = j / NW4;                  // 0..2 (compile-time divisor)
        off = j - w * NW4;
        src = (w == 0) ? w0 : (w == 1) ? w1 : w2;
        dst = wh + (size_t)w * (P_ * D_);
    }
    float4 v = ((const float4*)src)[off];
    __half2 h0 = __floats2half2_rn(v.x, v.y);
    __half2 h1 = __floats2half2_rn(v.z, v.w);
    ((uint2*)dst)[off] = make_uint2(*(uint32_t*)&h0, *(uint32_t*)&h1);
}

// ---------------- V transpose (half): Vt[b][p][s] = V[b][s][p] ----------------
__global__ __launch_bounds__(256) void transpose_sp(
    const __half* __restrict__ V, __half* __restrict__ Vt)
{
    __shared__ __half t[32][34];
    const int b = blockIdx.z;
    const int s0 = blockIdx.x * 32, p0 = blockIdx.y * 32;
    const __half* Vb = V + (size_t)b * S_ * P_;
    __half* Vtb = Vt + (size_t)b * S_ * P_;
    const int x = threadIdx.x, y = threadIdx.y;
    #pragma unroll
    for (int i = 0; i < 32; i += 8)
        t[y + i][x] = Vb[(size_t)(s0 + y + i) * P_ + p0 + x];
    __syncthreads();
    #pragma unroll
    for (int i = 0; i < 32; i += 8)
        Vtb[(size_t)(p0 + y + i) * S_ + s0 + x] = t[x][y + i];
}

// ---------------- causal softmax: fp32 scores -> half weights ----------------
__global__ __launch_bounds__(256) void causal_softmax(
    const float* __restrict__ S, __half* __restrict__ W, int n)
{
    const int q = blockIdx.x;
    const float* row = S + ((long long)blockIdx.y * n + q) * (long long)n;
    __half* wrow = W + ((long long)blockIdx.y * n + q) * (long long)n;
    const int tid = threadIdx.x;
    const int wid = tid >> 5, lane = tid & 31;
    const float scale = 0.03125f;   // 1/sqrt(1024)
    const int cnt = q + 1;

    float vals[8];
    float mx = -1e30f;
    int ni = 0;
    for (int k = tid; k < cnt; k += 256, ++ni) {
        vals[ni] = row[k] * scale;
        mx = fmaxf(mx, vals[ni]);
    }

    __shared__ float red[8];
    #pragma unroll
    for (int o = 16; o > 0; o >>= 1) mx = fmaxf(mx, __shfl_xor_sync(0xffffffffu, mx, o));
    if (lane == 0) red[wid] = mx;
    __syncthreads();
    mx = red[0];
    #pragma unroll
    for (int w = 1; w < 8; w++) mx = fmaxf(mx, red[w]);
    __syncthreads();

    float sum = 0.f;
    #pragma unroll 8
    for (int i = 0; i < ni; ++i) {
        vals[i] = __expf(vals[i] - mx);
        sum += vals[i];
    }
    #pragma unroll
    for (int o = 16; o > 0; o >>= 1) sum += __shfl_xor_sync(0xffffffffu, sum, o);
    if (lane == 0) red[wid] = sum;
    __syncthreads();
    sum = red[0];
    #pragma unroll
    for (int w = 1; w < 8; w++) sum += red[w];
    const float inv = 1.f / sum;

    {
        int i = 0;
        for (int k = tid; k < cnt; k += 256, ++i)
            wrow[k] = __float2half_rn(vals[i] * inv);
    }
    const int lim = ((q / BM) + 1) * BM;
    for (int k = cnt + tid; k < lim; k += 256) wrow[k] = __float2half_rn(0.f);
}

// ---------------- launcher ----------------
extern "C" void kernel_launch(void* const* d_in, const int* in_sizes, int n_in,
                              void* d_out, int out_size)
{
    const float* x  = (const float*)d_in[0];
    const float* Wq = (const float*)d_in[1];
    const float* Wk = (const float*)d_in[2];
    const float* Wv = (const float*)d_in[3];
    float* out = (float*)d_out;

    __half *Q, *K, *V, *Vt, *Wgt, *xh, *Wh;
    float *Sc;
    cudaGetSymbolAddress((void**)&Q,   g_Q);
    cudaGetSymbolAddress((void**)&K,   g_K);
    cudaGetSymbolAddress((void**)&V,   g_V);
    cudaGetSymbolAddress((void**)&Vt,  g_Vt);
    cudaGetSymbolAddress((void**)&Wgt, g_W);
    cudaGetSymbolAddress((void**)&Sc,  g_S);
    cudaGetSymbolAddress((void**)&xh,  g_xh);
    cudaGetSymbolAddress((void**)&Wh,  g_Wh);
    __half* Wqh = Wh;
    __half* Wkh = Wh + (size_t)P_ * D_;
    __half* Wvh = Wh + 2 * (size_t)P_ * D_;

    cudaFuncSetAttribute(gemm_nt_h, cudaFuncAttributeMaxDynamicSharedMemorySize, SMEM_BYTES);

    // convert all inputs to fp16 in one launch
    const int tot4 = NX4 + 3 * NW4;
    to_half_all<<<(tot4 + 255) / 256, 256>>>(x, xh, Wq, Wk, Wv, Wh);

    dim3 blk(NT_);

    // merged QKV projections (z selects weight/output), half outputs
    dim3 gproj(P_ / BN, (B_ * S_) / BM, 3);
    gemm_nt_h<<<gproj, blk, SMEM_BYTES>>>(xh, Wqh, Wkh, Wvh,
                                          nullptr, Q, K, V,
                                          B_ * S_, P_, D_, 0, 0, 0, 0, 0, 0, 1);

    // V transpose for the NT-form Z gemm
    transpose_sp<<<dim3(S_ / 32, P_ / 32, B_), dim3(32, 8)>>>(V, Vt);

    // scores = Q @ K^T per batch (causal tile skip), fp32 out
    dim3 gsc(S_ / BN, S_ / BM, B_);
    gemm_nt_h<<<gsc, blk, SMEM_BYTES>>>(Q, K, nullptr, nullptr,
                                        Sc, nullptr, nullptr, nullptr,
                                        S_, S_, P_,
                                        (long long)S_ * P_, (long long)S_ * P_,
                                        (long long)S_ * S_, 1, 1, 0, 0);

    // causal softmax -> half weights (+ zero-fill to tile boundary)
    causal_softmax<<<dim3(S_, B_), 256>>>(Sc, Wgt, S_);

    // Z = weights @ Vt^T per batch, k truncated to causal band, fp32 out
    dim3 gz(P_ / BN, S_ / BM, B_);
    gemm_nt_h<<<gz, blk, SMEM_BYTES>>>(Wgt, Vt, nullptr, nullptr,
                                       out, nullptr, nullptr, nullptr,
                                       S_, P_, S_,
                                       (long long)S_ * S_, (long long)S_ * P_,
                                       (long long)S_ * P_, 1, 0, 1, 0);
}

// round 8
// speedup vs baseline: 7.1549x; 1.5346x over previous
#include <cuda_runtime.h>
#include <cuda_fp16.h>
#include <cstdint>

#define B_ 4
#define S_ 2048
#define D_ 1024
#define P_ 1024

#define BM 128
#define BN 128
#define BK 64                        // halves of k per chunk (128B/row)
#define NT_ 256
#define NSTAGE 3
#define BKH 72                       // padded row stride in halves (144B)
#define TILE_H (BM * BKH)
#define STAGE_BYTES (2 * TILE_H * 2) // A+B tiles = 36864
#define SMEM_BYTES (NSTAGE * STAGE_BYTES)  // 110592 -> 2 CTAs/SM

#define NX4 ((B_ * S_ * D_) / 4)
#define NW4 ((P_ * D_) / 4)

// Scratch (static device arrays; no dynamic allocation anywhere).
__device__ __half g_Q  [(size_t)B_ * S_ * P_];
__device__ __half g_K  [(size_t)B_ * S_ * P_];
__device__ __half g_V  [(size_t)B_ * S_ * P_];
__device__ __half g_Vt [(size_t)B_ * S_ * P_];
__device__ __half g_W  [(size_t)B_ * S_ * S_];
__device__ float  g_S  [(size_t)B_ * S_ * S_];
__device__ __half g_xh [(size_t)B_ * S_ * D_];
__device__ __half g_Wh [3][(size_t)P_ * D_];

__device__ __forceinline__ uint32_t smem_u32(const void* p) {
    uint32_t a;
    asm("{ .reg .u64 t; cvta.to.shared.u64 t, %1; cvt.u32.u64 %0, t; }" : "=r"(a) : "l"(p));
    return a;
}
__device__ __forceinline__ void cp16(uint32_t dst, const void* src) {
    asm volatile("cp.async.cg.shared.global [%0], [%1], 16;" :: "r"(dst), "l"(src));
}
#define CP_COMMIT() asm volatile("cp.async.commit_group;" ::: "memory")
#define CP_WAIT(n)  asm volatile("cp.async.wait_group %0;" :: "n"(n) : "memory")

#define LDSM4(r0, r1, r2, r3, a)                                                  \
    asm volatile("ldmatrix.sync.aligned.m8n8.x4.shared.b16 {%0,%1,%2,%3}, [%4];"  \
        : "=r"(r0), "=r"(r1), "=r"(r2), "=r"(r3) : "r"(a))

__device__ __forceinline__ void mma_f16(float* c, const uint32_t* a,
                                        uint32_t b0, uint32_t b1) {
    asm volatile(
        "mma.sync.aligned.m16n8k16.row.col.f32.f16.f16.f32 "
        "{%0,%1,%2,%3}, {%4,%5,%6,%7}, {%8,%9}, {%0,%1,%2,%3};"
        : "+f"(c[0]), "+f"(c[1]), "+f"(c[2]), "+f"(c[3])
        : "r"(a[0]), "r"(a[1]), "r"(a[2]), "r"(a[3]), "r"(b0), "r"(b1));
}

// C[m,n] = sum_k A[m,k] * B[n,k]; A,B half row-major; C fp32 or fp16.
__global__ __launch_bounds__(NT_, 2) void gemm_nt_h(
    const __half* __restrict__ A,
    const __half* __restrict__ B0, const __half* __restrict__ B1, const __half* __restrict__ B2,
    float* __restrict__ Cf, __half* __restrict__ Ch0, __half* __restrict__ Ch1, __half* __restrict__ Ch2,
    int M, int N, int K, long long sA, long long sB, long long sC,
    int mode, int causal, int klim, int out_half)
{
    extern __shared__ char smraw[];
    const int m0 = blockIdx.y * BM;
    const int n0 = blockIdx.x * BN;
    if (causal && n0 > m0) return;

    const __half* B;
    float* Cf_ = Cf;
    __half* Ch_ = Ch0;
    if (mode == 0) {
        B   = (blockIdx.z == 0) ? B0 : (blockIdx.z == 1) ? B1 : B2;
        Ch_ = (blockIdx.z == 0) ? Ch0 : (blockIdx.z == 1) ? Ch1 : Ch2;
    } else {
        A += (long long)blockIdx.z * sA;
        B = B0 + (long long)blockIdx.z * sB;
        if (out_half) Ch_ = Ch0 + (long long)blockIdx.z * sC;
        else          Cf_ = Cf  + (long long)blockIdx.z * sC;
    }

    const int kmax = klim ? min(K, m0 + BM) : K;
    const int nchunk = kmax / BK;

    const int tid = threadIdx.x;
    const int wid = tid >> 5, lane = tid & 31;
    const int g = lane >> 2, tg = lane & 3;
    const int wm = (wid >> 2) * 64;
    const int wn = (wid & 3) * 32;

    const uint32_t sbase = smem_u32(smraw);
    const __half* Abase = A + (size_t)m0 * K;
    const __half* Bbase = B + (size_t)n0 * K;

    uint32_t offA[4], offB[2];
    {
        const int rA = lane & 15;
        const int cA = (lane >> 4) * 16;
        #pragma unroll
        for (int mt = 0; mt < 4; mt++)
            offA[mt] = (uint32_t)((wm + mt * 16 + rA) * BKH) * 2u + cA;
        const int rB = (lane & 7) + ((lane >> 4) << 3);
        const int cB = ((lane >> 3) & 1) * 16;
        #pragma unroll
        for (int gb = 0; gb < 2; gb++)
            offB[gb] = (uint32_t)(TILE_H * 2) +
                       (uint32_t)((wn + gb * 16 + rB) * BKH) * 2u + cB;
    }

    float acc[4][4][4];
    #pragma unroll
    for (int i = 0; i < 4; i++)
        #pragma unroll
        for (int j = 0; j < 4; j++)
            #pragma unroll
            for (int r = 0; r < 4; r++) acc[i][j][r] = 0.f;

    auto load_stage = [&](int c, int s) {
        const uint32_t ab = sbase + (uint32_t)s * STAGE_BYTES;
        const uint32_t bb = ab + TILE_H * 2u;
        const __half* Ag = Abase + (size_t)c * BK;
        const __half* Bg = Bbase + (size_t)c * BK;
        #pragma unroll
        for (int j = 0; j < 4; j++) {
            int idx = j * NT_ + tid;
            int row = idx >> 3;
            int kc = (idx & 7) * 8;
            uint32_t doff = (uint32_t)(row * BKH + kc) * 2u;
            cp16(ab + doff, Ag + (size_t)row * K + kc);
            cp16(bb + doff, Bg + (size_t)row * K + kc);
        }
    };

    load_stage(0, 0);
    CP_COMMIT();
    load_stage(1, 1);
    CP_COMMIT();

    // double-buffered fragments
    uint32_t af[2][4][4], bf[2][2][4];

    auto ldsm_step = [&](uint32_t stb, int kk, int buf) {
        const uint32_t ko = (uint32_t)kk * 32u;
        #pragma unroll
        for (int mt = 0; mt < 4; mt++)
            LDSM4(af[buf][mt][0], af[buf][mt][1], af[buf][mt][2], af[buf][mt][3],
                  stb + offA[mt] + ko);
        #pragma unroll
        for (int gb = 0; gb < 2; gb++)
            LDSM4(bf[buf][gb][0], bf[buf][gb][1], bf[buf][gb][2], bf[buf][gb][3],
                  stb + offB[gb] + ko);
    };
    auto mma_step = [&](int buf) {
        #pragma unroll
        for (int mt = 0; mt < 4; mt++)
            #pragma unroll
            for (int nt = 0; nt < 4; nt++)
                mma_f16(acc[mt][nt], af[buf][mt],
                        bf[buf][nt >> 1][(nt & 1) * 2], bf[buf][nt >> 1][(nt & 1) * 2 + 1]);
    };

    int sc = 0;
    for (int i = 0; i < nchunk; i++) {
        CP_WAIT(1);
        __syncthreads();

        const int c2 = i + 2;
        if (c2 < nchunk) load_stage(c2, c2 % NSTAGE);
        CP_COMMIT();

        const uint32_t stb = sbase + (uint32_t)sc * STAGE_BYTES;
        ldsm_step(stb, 0, 0);
        #pragma unroll
        for (int kk = 0; kk < 4; kk++) {
            const int cur = kk & 1;
            if (kk < 3) ldsm_step(stb, kk + 1, cur ^ 1);  // prefetch next frags
            mma_step(cur);                                 // consume current
        }
        if (++sc == NSTAGE) sc = 0;
    }

    #pragma unroll
    for (int mt = 0; mt < 4; mt++) {
        #pragma unroll
        for (int nt = 0; nt < 4; nt++) {
            const int row = m0 + wm + mt * 16 + g;
            const int col = n0 + wn + nt * 8 + tg * 2;
            if (out_half) {
                *(__half2*)(Ch_ + (size_t)row * N + col) =
                    __floats2half2_rn(acc[mt][nt][0], acc[mt][nt][1]);
                *(__half2*)(Ch_ + (size_t)(row + 8) * N + col) =
                    __floats2half2_rn(acc[mt][nt][2], acc[mt][nt][3]);
            } else {
                *(float2*)(Cf_ + (size_t)row * N + col) =
                    make_float2(acc[mt][nt][0], acc[mt][nt][1]);
                *(float2*)(Cf_ + (size_t)(row + 8) * N + col) =
                    make_float2(acc[mt][nt][2], acc[mt][nt][3]);
            }
        }
    }
}

// ---------------- fp32 -> fp16 conversion, one launch ----------------
__global__ __launch_bounds__(256) void to_half_all(
    const float* __restrict__ x,  __half* __restrict__ xh,
    const float* __restrict__ w0, const float* __restrict__ w1, const float* __restrict__ w2,
    __half* __restrict__ wh)
{
    int i = blockIdx.x * 256 + threadIdx.x;
    const float* src;
    __half* dst;
    int off;
    if (i < NX4) { src = x; dst = xh; off = i; }
    else {
        int j = i - NX4;
        int w = j / NW4;
        off = j - w * NW4;
        src = (w == 0) ? w0 : (w == 1) ? w1 : w2;
        dst = wh + (size_t)w * (P_ * D_);
    }
    float4 v = ((const float4*)src)[off];
    __half2 h0 = __floats2half2_rn(v.x, v.y);
    __half2 h1 = __floats2half2_rn(v.z, v.w);
    ((uint2*)dst)[off] = make_uint2(*(uint32_t*)&h0, *(uint32_t*)&h1);
}

// ---------------- V transpose (half) ----------------
__global__ __launch_bounds__(256) void transpose_sp(
    const __half* __restrict__ V, __half* __restrict__ Vt)
{
    __shared__ __half t[32][34];
    const int b = blockIdx.z;
    const int s0 = blockIdx.x * 32, p0 = blockIdx.y * 32;
    const __half* Vb = V + (size_t)b * S_ * P_;
    __half* Vtb = Vt + (size_t)b * S_ * P_;
    const int x = threadIdx.x, y = threadIdx.y;
    #pragma unroll
    for (int i = 0; i < 32; i += 8)
        t[y + i][x] = Vb[(size_t)(s0 + y + i) * P_ + p0 + x];
    __syncthreads();
    #pragma unroll
    for (int i = 0; i < 32; i += 8)
        Vtb[(size_t)(p0 + y + i) * S_ + s0 + x] = t[x][y + i];
}

// ---------------- causal softmax ----------------
__global__ __launch_bounds__(256) void causal_softmax(
    const float* __restrict__ S, __half* __restrict__ W, int n)
{
    const int q = blockIdx.x;
    const float* row = S + ((long long)blockIdx.y * n + q) * (long long)n;
    __half* wrow = W + ((long long)blockIdx.y * n + q) * (long long)n;
    const int tid = threadIdx.x;
    const int wid = tid >> 5, lane = tid & 31;
    const float scale = 0.03125f;
    const int cnt = q + 1;

    float vals[8];
    float mx = -1e30f;
    int ni = 0;
    for (int k = tid; k < cnt; k += 256, ++ni) {
        vals[ni] = row[k] * scale;
        mx = fmaxf(mx, vals[ni]);
    }

    __shared__ float red[8];
    #pragma unroll
    for (int o = 16; o > 0; o >>= 1) mx = fmaxf(mx, __shfl_xor_sync(0xffffffffu, mx, o));
    if (lane == 0) red[wid] = mx;
    __syncthreads();
    mx = red[0];
    #pragma unroll
    for (int w = 1; w < 8; w++) mx = fmaxf(mx, red[w]);
    __syncthreads();

    float sum = 0.f;
    #pragma unroll 8
    for (int i = 0; i < ni; ++i) {
        vals[i] = __expf(vals[i] - mx);
        sum += vals[i];
    }
    #pragma unroll
    for (int o = 16; o > 0; o >>= 1) sum += __shfl_xor_sync(0xffffffffu, sum, o);
    if (lane == 0) red[wid] = sum;
    __syncthreads();
    sum = red[0];
    #pragma unroll
    for (int w = 1; w < 8; w++) sum += red[w];
    const float inv = 1.f / sum;

    {
        int i = 0;
        for (int k = tid; k < cnt; k += 256, ++i)
            wrow[k] = __float2half_rn(vals[i] * inv);
    }
    const int lim = ((q / BM) + 1) * BM;
    for (int k = cnt + tid; k < lim; k += 256) wrow[k] = __float2half_rn(0.f);
}

// ---------------- launcher ----------------
extern "C" void kernel_launch(void* const* d_in, const int* in_sizes, int n_in,
                              void* d_out, int out_size)
{
    const float* x  = (const float*)d_in[0];
    const float* Wq = (const float*)d_in[1];
    const float* Wk = (const float*)d_in[2];
    const float* Wv = (const float*)d_in[3];
    float* out = (float*)d_out;

    __half *Q, *K, *V, *Vt, *Wgt, *xh, *Wh;
    float *Sc;
    cudaGetSymbolAddress((void**)&Q,   g_Q);
    cudaGetSymbolAddress((void**)&K,   g_K);
    cudaGetSymbolAddress((void**)&V,   g_V);
    cudaGetSymbolAddress((void**)&Vt,  g_Vt);
    cudaGetSymbolAddress((void**)&Wgt, g_W);
    cudaGetSymbolAddress((void**)&Sc,  g_S);
    cudaGetSymbolAddress((void**)&xh,  g_xh);
    cudaGetSymbolAddress((void**)&Wh,  g_Wh);
    __half* Wqh = Wh;
    __half* Wkh = Wh + (size_t)P_ * D_;
    __half* Wvh = Wh + 2 * (size_t)P_ * D_;

    cudaFuncSetAttribute(gemm_nt_h, cudaFuncAttributeMaxDynamicSharedMemorySize, SMEM_BYTES);

    const int tot4 = NX4 + 3 * NW4;
    to_half_all<<<(tot4 + 255) / 256, 256>>>(x, xh, Wq, Wk, Wv, Wh);

    dim3 blk(NT_);

    dim3 gproj(P_ / BN, (B_ * S_) / BM, 3);
    gemm_nt_h<<<gproj, blk, SMEM_BYTES>>>(xh, Wqh, Wkh, Wvh,
                                          nullptr, Q, K, V,
                                          B_ * S_, P_, D_, 0, 0, 0, 0, 0, 0, 1);

    transpose_sp<<<dim3(S_ / 32, P_ / 32, B_), dim3(32, 8)>>>(V, Vt);

    dim3 gsc(S_ / BN, S_ / BM, B_);
    gemm_nt_h<<<gsc, blk, SMEM_BYTES>>>(Q, K, nullptr, nullptr,
                                        Sc, nullptr, nullptr, nullptr,
                                        S_, S_, P_,
                                        (long long)S_ * P_, (long long)S_ * P_,
                                        (long long)S_ * S_, 1, 1, 0, 0);

    causal_softmax<<<dim3(S_, B_), 256>>>(Sc, Wgt, S_);

    dim3 gz(P_ / BN, S_ / BM, B_);
    gemm_nt_h<<<gz, blk, SMEM_BYTES>>>(Wgt, Vt, nullptr, nullptr,
                                       out, nullptr, nullptr, nullptr,
                                       S_, P_, S_,
                                       (long long)S_ * S_, (long long)S_ * P_,
                                       (long long)S_ * P_, 1, 0, 1, 0);
}

// round 9
// speedup vs baseline: 7.3250x; 1.0238x over previous
#include <cuda_runtime.h>
#include <cuda_fp16.h>
#include <cstdint>

#define B_ 4
#define S_ 2048
#define D_ 1024
#define P_ 1024

#define BM 128
#define BN 128
#define BK 64                        // halves of k per chunk
#define NT_ 256
#define NSTAGE 3
#define BKH 72                       // A/B k-major row stride in halves (144B)
#define BTN 136                      // bt-mode B row stride in halves (272B)
#define TILE_H (BM * BKH)
#define A_TILE_B (TILE_H * 2)        // 18432
#define STAGE_BYTES (2 * A_TILE_B)   // 36864 (bt-mode B tile 64*272=17408 fits)
#define SMEM_BYTES (NSTAGE * STAGE_BYTES)  // 110592 -> 2 CTAs/SM

#define NX4 ((B_ * S_ * D_) / 4)
#define NW4 ((P_ * D_) / 4)

// Scratch (static device arrays; no dynamic allocation anywhere).
__device__ __half g_Q  [(size_t)B_ * S_ * P_];
__device__ __half g_K  [(size_t)B_ * S_ * P_];
__device__ __half g_V  [(size_t)B_ * S_ * P_];
__device__ __half g_W  [(size_t)B_ * S_ * S_];
__device__ float  g_S  [(size_t)B_ * S_ * S_];
__device__ __half g_xh [(size_t)B_ * S_ * D_];
__device__ __half g_Wh [3][(size_t)P_ * D_];

__device__ __forceinline__ uint32_t smem_u32(const void* p) {
    uint32_t a;
    asm("{ .reg .u64 t; cvta.to.shared.u64 t, %1; cvt.u32.u64 %0, t; }" : "=r"(a) : "l"(p));
    return a;
}
__device__ __forceinline__ void cp16(uint32_t dst, const void* src) {
    asm volatile("cp.async.cg.shared.global [%0], [%1], 16;" :: "r"(dst), "l"(src));
}
#define CP_COMMIT() asm volatile("cp.async.commit_group;" ::: "memory")
#define CP_WAIT(n)  asm volatile("cp.async.wait_group %0;" :: "n"(n) : "memory")

#define LDSM4(r0, r1, r2, r3, a)                                                  \
    asm volatile("ldmatrix.sync.aligned.m8n8.x4.shared.b16 {%0,%1,%2,%3}, [%4];"  \
        : "=r"(r0), "=r"(r1), "=r"(r2), "=r"(r3) : "r"(a))
#define LDSM4T(r0, r1, r2, r3, a)                                                 \
    asm volatile("ldmatrix.sync.aligned.m8n8.x4.trans.shared.b16 {%0,%1,%2,%3}, [%4];" \
        : "=r"(r0), "=r"(r1), "=r"(r2), "=r"(r3) : "r"(a))

__device__ __forceinline__ void mma_f16(float* c, const uint32_t* a,
                                        uint32_t b0, uint32_t b1) {
    asm volatile(
        "mma.sync.aligned.m16n8k16.row.col.f32.f16.f16.f32 "
        "{%0,%1,%2,%3}, {%4,%5,%6,%7}, {%8,%9}, {%0,%1,%2,%3};"
        : "+f"(c[0]), "+f"(c[1]), "+f"(c[2]), "+f"(c[3])
        : "r"(a[0]), "r"(a[1]), "r"(a[2]), "r"(a[3]), "r"(b0), "r"(b1));
}

// bt=0: C[m,n] = sum_k A[m,k] * B[n,k] (B row-major [N,K])
// bt=1: C[m,n] = sum_k A[m,k] * B[k,n] (B row-major [K,N], ldmatrix.trans path)
// mode 0 (projections): z selects B0/B1/B2 -> Ch0/Ch1/Ch2 (half out).
// mode 1: A += z*sA, B = B0 + z*sB, C = z-strided; out_half selects type.
__global__ __launch_bounds__(NT_, 2) void gemm_nt_h(
    const __half* __restrict__ A,
    const __half* __restrict__ B0, const __half* __restrict__ B1, const __half* __restrict__ B2,
    float* __restrict__ Cf, __half* __restrict__ Ch0, __half* __restrict__ Ch1, __half* __restrict__ Ch2,
    int M, int N, int K, long long sA, long long sB, long long sC,
    int mode, int causal, int klim, int out_half, int bt)
{
    extern __shared__ char smraw[];
    const int m0 = blockIdx.y * BM;
    const int n0 = blockIdx.x * BN;
    if (causal && n0 > m0) return;

    const __half* B;
    float* Cf_ = Cf;
    __half* Ch_ = Ch0;
    if (mode == 0) {
        B   = (blockIdx.z == 0) ? B0 : (blockIdx.z == 1) ? B1 : B2;
        Ch_ = (blockIdx.z == 0) ? Ch0 : (blockIdx.z == 1) ? Ch1 : Ch2;
    } else {
        A += (long long)blockIdx.z * sA;
        B = B0 + (long long)blockIdx.z * sB;
        if (out_half) Ch_ = Ch0 + (long long)blockIdx.z * sC;
        else          Cf_ = Cf  + (long long)blockIdx.z * sC;
    }

    const int kmax = klim ? min(K, m0 + BM) : K;
    const int nchunk = kmax / BK;

    const int tid = threadIdx.x;
    const int wid = tid >> 5, lane = tid & 31;
    const int g = lane >> 2, tg = lane & 3;
    const int wm = (wid >> 2) * 64;
    const int wn = (wid & 3) * 32;

    const uint32_t sbase = smem_u32(smraw);
    const __half* Abase = A + (size_t)m0 * K;

    uint32_t offA[4], offB[2];
    {
        const int rA = lane & 15;
        const int cA = (lane >> 4) * 16;
        #pragma unroll
        for (int mt = 0; mt < 4; mt++)
            offA[mt] = (uint32_t)((wm + mt * 16 + rA) * BKH) * 2u + cA;
        if (!bt) {
            // B [n][k] k-major: non-trans LDSM
            const int rB = (lane & 7) + ((lane >> 4) << 3);
            const int cB = ((lane >> 3) & 1) * 16;
            #pragma unroll
            for (int gb = 0; gb < 2; gb++)
                offB[gb] = (uint32_t)A_TILE_B +
                           (uint32_t)((wn + gb * 16 + rB) * BKH) * 2u + cB;
        } else {
            // B [k][n] n-major: trans LDSM; lane-groups: k0-7/octA, k8-15/octA, k0-7/octB, k8-15/octB
            const int rK = (lane & 7) + (((lane >> 3) & 1) << 3);   // k row within 16
            const int oc = (lane >> 4) * 8;                          // n octet offset
            #pragma unroll
            for (int gb = 0; gb < 2; gb++)
                offB[gb] = (uint32_t)A_TILE_B +
                           (uint32_t)(rK * BTN + wn + gb * 16 + oc) * 2u;
        }
    }

    float acc[4][4][4];
    #pragma unroll
    for (int i = 0; i < 4; i++)
        #pragma unroll
        for (int j = 0; j < 4; j++)
            #pragma unroll
            for (int r = 0; r < 4; r++) acc[i][j][r] = 0.f;

    auto load_stage = [&](int c, int s) {
        const uint32_t ab = sbase + (uint32_t)s * STAGE_BYTES;
        const uint32_t bb = ab + A_TILE_B;
        const __half* Ag = Abase + (size_t)c * BK;
        #pragma unroll
        for (int j = 0; j < 4; j++) {
            int idx = j * NT_ + tid;
            int row = idx >> 3;
            int kc = (idx & 7) * 8;
            cp16(ab + (uint32_t)(row * BKH + kc) * 2u, Ag + (size_t)row * K + kc);
        }
        if (!bt) {
            const __half* Bg = B + (size_t)n0 * K + (size_t)c * BK;
            #pragma unroll
            for (int j = 0; j < 4; j++) {
                int idx = j * NT_ + tid;
                int row = idx >> 3;
                int kc = (idx & 7) * 8;
                cp16(bb + (uint32_t)(row * BKH + kc) * 2u, Bg + (size_t)row * K + kc);
            }
        } else {
            // tile [64 k][128 n] from B[k][n], row stride N
            const __half* Bg = B + (size_t)c * BK * N + n0;
            #pragma unroll
            for (int j = 0; j < 4; j++) {
                int idx = j * NT_ + tid;
                int row = idx >> 4;             // 0..63 k-row
                int nc = (idx & 15) * 8;        // halves 0..120
                cp16(bb + (uint32_t)(row * BTN + nc) * 2u, Bg + (size_t)row * N + nc);
            }
        }
    };

    load_stage(0, 0);
    CP_COMMIT();
    load_stage(1, 1);
    CP_COMMIT();

    uint32_t af[2][4][4], bf[2][2][4];

    auto ldsm_step = [&](uint32_t stb, int kk, int buf) {
        const uint32_t koA = (uint32_t)kk * 32u;
        #pragma unroll
        for (int mt = 0; mt < 4; mt++)
            LDSM4(af[buf][mt][0], af[buf][mt][1], af[buf][mt][2], af[buf][mt][3],
                  stb + offA[mt] + koA);
        if (!bt) {
            #pragma unroll
            for (int gb = 0; gb < 2; gb++)
                LDSM4(bf[buf][gb][0], bf[buf][gb][1], bf[buf][gb][2], bf[buf][gb][3],
                      stb + offB[gb] + koA);
        } else {
            const uint32_t koB = (uint32_t)kk * (16u * BTN * 2u);
            #pragma unroll
            for (int gb = 0; gb < 2; gb++)
                LDSM4T(bf[buf][gb][0], bf[buf][gb][1], bf[buf][gb][2], bf[buf][gb][3],
                       stb + offB[gb] + koB);
        }
    };
    auto mma_step = [&](int buf) {
        #pragma unroll
        for (int mt = 0; mt < 4; mt++)
            #pragma unroll
            for (int nt = 0; nt < 4; nt++)
                mma_f16(acc[mt][nt], af[buf][mt],
                        bf[buf][nt >> 1][(nt & 1) * 2], bf[buf][nt >> 1][(nt & 1) * 2 + 1]);
    };

    int sc = 0;
    for (int i = 0; i < nchunk; i++) {
        CP_WAIT(1);
        __syncthreads();

        const int c2 = i + 2;
        if (c2 < nchunk) load_stage(c2, c2 % NSTAGE);
        CP_COMMIT();

        const uint32_t stb = sbase + (uint32_t)sc * STAGE_BYTES;
        ldsm_step(stb, 0, 0);
        #pragma unroll
        for (int kk = 0; kk < 4; kk++) {
            const int cur = kk & 1;
            if (kk < 3) ldsm_step(stb, kk + 1, cur ^ 1);
            mma_step(cur);
        }
        if (++sc == NSTAGE) sc = 0;
    }

    #pragma unroll
    for (int mt = 0; mt < 4; mt++) {
        #pragma unroll
        for (int nt = 0; nt < 4; nt++) {
            const int row = m0 + wm + mt * 16 + g;
            const int col = n0 + wn + nt * 8 + tg * 2;
            if (out_half) {
                *(__half2*)(Ch_ + (size_t)row * N + col) =
                    __floats2half2_rn(acc[mt][nt][0], acc[mt][nt][1]);
                *(__half2*)(Ch_ + (size_t)(row + 8) * N + col) =
                    __floats2half2_rn(acc[mt][nt][2], acc[mt][nt][3]);
            } else {
                *(float2*)(Cf_ + (size_t)row * N + col) =
                    make_float2(acc[mt][nt][0], acc[mt][nt][1]);
                *(float2*)(Cf_ + (size_t)(row + 8) * N + col) =
                    make_float2(acc[mt][nt][2], acc[mt][nt][3]);
            }
        }
    }
}

// ---------------- fp32 -> fp16 conversion, one launch ----------------
__global__ __launch_bounds__(256) void to_half_all(
    const float* __restrict__ x,  __half* __restrict__ xh,
    const float* __restrict__ w0, const float* __restrict__ w1, const float* __restrict__ w2,
    __half* __restrict__ wh)
{
    int i = blockIdx.x * 256 + threadIdx.x;
    const float* src;
    __half* dst;
    int off;
    if (i < NX4) { src = x; dst = xh; off = i; }
    else {
        int j = i - NX4;
        int w = j / NW4;
        off = j - w * NW4;
        src = (w == 0) ? w0 : (w == 1) ? w1 : w2;
        dst = wh + (size_t)w * (P_ * D_);
    }
    float4 v = ((const float4*)src)[off];
    __half2 h0 = __floats2half2_rn(v.x, v.y);
    __half2 h1 = __floats2half2_rn(v.z, v.w);
    ((uint2*)dst)[off] = make_uint2(*(uint32_t*)&h0, *(uint32_t*)&h1);
}

// ---------------- causal softmax: fp32 scores -> half weights (vectorized) ----------------
__global__ __launch_bounds__(256) void causal_softmax(
    const float* __restrict__ S, __half* __restrict__ W, int n)
{
    const int q = blockIdx.x;
    const float* row = S + ((long long)blockIdx.y * n + q) * (long long)n;
    __half* wrow = W + ((long long)blockIdx.y * n + q) * (long long)n;
    const int tid = threadIdx.x;
    const int wid = tid >> 5, lane = tid & 31;
    const float scale = 0.03125f;   // 1/sqrt(1024)
    const int cnt = q + 1;
    const int lim = ((q >> 7) + 1) << 7;   // next multiple of 128 (tile boundary)

    float vals[8];                         // lim <= 2048 -> <= 2 float4 per thread
    float mx = -1e30f;
    int nv = 0;
    for (int base = tid * 4; base < lim; base += 1024, nv += 4) {
        float4 v = *(const float4*)(row + base);   // in-bounds (row has n floats)
        float x0 = (base + 0 < cnt) ? v.x * scale : -1e30f;
        float x1 = (base + 1 < cnt) ? v.y * scale : -1e30f;
        float x2 = (base + 2 < cnt) ? v.z * scale : -1e30f;
        float x3 = (base + 3 < cnt) ? v.w * scale : -1e30f;
        vals[nv] = x0; vals[nv + 1] = x1; vals[nv + 2] = x2; vals[nv + 3] = x3;
        mx = fmaxf(mx, fmaxf(fmaxf(x0, x1), fmaxf(x2, x3)));
    }

    __shared__ float red[8];
    #pragma unroll
    for (int o = 16; o > 0; o >>= 1) mx = fmaxf(mx, __shfl_xor_sync(0xffffffffu, mx, o));
    if (lane == 0) red[wid] = mx;
    __syncthreads();
    mx = red[0];
    #pragma unroll
    for (int w = 1; w < 8; w++) mx = fmaxf(mx, red[w]);
    __syncthreads();

    float sum = 0.f;
    #pragma unroll
    for (int i = 0; i < nv; ++i) {
        vals[i] = __expf(vals[i] - mx);    // masked lanes: exp(-1e30) == 0
        sum += vals[i];
    }
    #pragma unroll
    for (int o = 16; o > 0; o >>= 1) sum += __shfl_xor_sync(0xffffffffu, sum, o);
    if (lane == 0) red[wid] = sum;
    __syncthreads();
    sum = red[0];
    #pragma unroll
    for (int w = 1; w < 8; w++) sum += red[w];
    const float inv = 1.f / sum;

    nv = 0;
    for (int base = tid * 4; base < lim; base += 1024, nv += 4) {
        __half2 h0 = __floats2half2_rn(vals[nv] * inv, vals[nv + 1] * inv);
        __half2 h1 = __floats2half2_rn(vals[nv + 2] * inv, vals[nv + 3] * inv);
        *(uint2*)(wrow + base) = make_uint2(*(uint32_t*)&h0, *(uint32_t*)&h1);
    }
}

// ---------------- launcher ----------------
extern "C" void kernel_launch(void* const* d_in, const int* in_sizes, int n_in,
                              void* d_out, int out_size)
{
    const float* x  = (const float*)d_in[0];
    const float* Wq = (const float*)d_in[1];
    const float* Wk = (const float*)d_in[2];
    const float* Wv = (const float*)d_in[3];
    float* out = (float*)d_out;

    __half *Q, *K, *V, *Wgt, *xh, *Wh;
    float *Sc;
    cudaGetSymbolAddress((void**)&Q,   g_Q);
    cudaGetSymbolAddress((void**)&K,   g_K);
    cudaGetSymbolAddress((void**)&V,   g_V);
    cudaGetSymbolAddress((void**)&Wgt, g_W);
    cudaGetSymbolAddress((void**)&Sc,  g_S);
    cudaGetSymbolAddress((void**)&xh,  g_xh);
    cudaGetSymbolAddress((void**)&Wh,  g_Wh);
    __half* Wqh = Wh;
    __half* Wkh = Wh + (size_t)P_ * D_;
    __half* Wvh = Wh + 2 * (size_t)P_ * D_;

    cudaFuncSetAttribute(gemm_nt_h, cudaFuncAttributeMaxDynamicSharedMemorySize, SMEM_BYTES);

    const int tot4 = NX4 + 3 * NW4;
    to_half_all<<<(tot4 + 255) / 256, 256>>>(x, xh, Wq, Wk, Wv, Wh);

    dim3 blk(NT_);

    // merged QKV projections (z selects weight/output), half outputs
    dim3 gproj(P_ / BN, (B_ * S_) / BM, 3);
    gemm_nt_h<<<gproj, blk, SMEM_BYTES>>>(xh, Wqh, Wkh, Wvh,
                                          nullptr, Q, K, V,
                                          B_ * S_, P_, D_, 0, 0, 0, 0, 0, 0, 1, 0);

    // scores = Q @ K^T per batch (causal tile skip), fp32 out
    dim3 gsc(S_ / BN, S_ / BM, B_);
    gemm_nt_h<<<gsc, blk, SMEM_BYTES>>>(Q, K, nullptr, nullptr,
                                        Sc, nullptr, nullptr, nullptr,
                                        S_, S_, P_,
                                        (long long)S_ * P_, (long long)S_ * P_,
                                        (long long)S_ * S_, 1, 1, 0, 0, 0);

    // causal softmax -> half weights (masked store covers zero-fill)
    causal_softmax<<<dim3(S_, B_), 256>>>(Sc, Wgt, S_);

    // Z = weights @ V per batch (bt=1: V consumed [k][n] via ldmatrix.trans),
    // k truncated to causal band, fp32 out
    dim3 gz(P_ / BN, S_ / BM, B_);
    gemm_nt_h<<<gz, blk, SMEM_BYTES>>>(Wgt, V, nullptr, nullptr,
                                       out, nullptr, nullptr, nullptr,
                                       S_, P_, S_,
                                       (long long)S_ * S_, (long long)S_ * P_,
                                       (long long)S_ * P_, 1, 0, 1, 0, 1);
}